// round 1
// baseline (speedup 1.0000x reference)
#include <cuda_runtime.h>
#include <math.h>

#define B_ 16384
#define S_ 336
#define T_ 48
#define IN_ 5
#define H_ 64
#define G_ 256          // 4*H
#define ROWS_ 16        // batch rows per CTA
#define THREADS_ 256    // 8 warps, 2 rows per warp

// SMEM layout in floats
#define OFF_W1   0          // 32768 floats: [32 quads][256 gates][4]  (Wih1 | Whh1 concat, k-interleaved)
#define OFF_W0H  32768      // 16384 floats: [16 quads][256][4]        (Whh0, k-interleaved)
#define OFF_W0X  49152      // 1280 floats: enc [5][256]; dec uses first 256 as vector
#define OFF_B0   50432      // 256: bih0+bhh0
#define OFF_B1   50688      // 256: bih1+bhh1
#define OFF_FCW  50944      // 64
#define OFF_HS0  51008      // 16*64 h of layer0
#define OFF_HS1  52032      // 16*64 h of layer1
#define SMEM_FLOATS 53056
#define SMEM_BYTES (SMEM_FLOATS * 4)

__device__ __forceinline__ float sigf(float x) { return 1.0f / (1.0f + __expf(-x)); }

__device__ __forceinline__ float cell_update(float gi, float gf, float gg, float go, float& c) {
    float i = sigf(gi), f = sigf(gf), g = tanhf(gg), o = sigf(go);
    c = f * c + i * g;
    return o * tanhf(c);
}

// W: [256][64] row-major (gate-major). Store k-interleaved-by-4:
// dst[(qoff + k/4)*1024 + g*4 + (k%4)]
__device__ __forceinline__ void load_matrix_interleaved(float* dst, const float* __restrict__ W, int qoff) {
    for (int i = threadIdx.x; i < G_ * H_; i += THREADS_) {
        int g = i >> 6, k = i & 63;
        dst[(qoff + (k >> 2)) * 1024 + (g << 2) + (k & 3)] = W[i];
    }
}

// Accumulate NQ k-quads: a[j] += sum_k h[k] * W[g=lane+32j][k]
template <int NQ>
__device__ __forceinline__ void gemv_quads(float* a0, float* a1, const float4* __restrict__ Wv,
                                           int qbase, const float4* hA, const float4* hB, int lane) {
#pragma unroll 4
    for (int q = 0; q < NQ; q++) {
        float4 ha = hA[q];
        float4 hb = hB[q];
        const float4* wrow = Wv + (qbase + q) * 256 + lane;
#pragma unroll
        for (int j = 0; j < 8; j++) {
            float4 w = wrow[32 * j];
            a0[j] = fmaf(ha.x, w.x, a0[j]);
            a0[j] = fmaf(ha.y, w.y, a0[j]);
            a0[j] = fmaf(ha.z, w.z, a0[j]);
            a0[j] = fmaf(ha.w, w.w, a0[j]);
            a1[j] = fmaf(hb.x, w.x, a1[j]);
            a1[j] = fmaf(hb.y, w.y, a1[j]);
            a1[j] = fmaf(hb.z, w.z, a1[j]);
            a1[j] = fmaf(hb.w, w.w, a1[j]);
        }
    }
}

__global__ void __launch_bounds__(THREADS_, 1)
seq2seq_kernel(const float* __restrict__ src,
               const float* __restrict__ eWih0, const float* __restrict__ eWhh0,
               const float* __restrict__ ebih0, const float* __restrict__ ebhh0,
               const float* __restrict__ eWih1, const float* __restrict__ eWhh1,
               const float* __restrict__ ebih1, const float* __restrict__ ebhh1,
               const float* __restrict__ dWih0, const float* __restrict__ dWhh0,
               const float* __restrict__ dbih0, const float* __restrict__ dbhh0,
               const float* __restrict__ dWih1, const float* __restrict__ dWhh1,
               const float* __restrict__ dbih1, const float* __restrict__ dbhh1,
               const float* __restrict__ fcW, const float* __restrict__ fcb,
               float* __restrict__ out) {
    extern __shared__ float sm[];
    const int tid = threadIdx.x;
    const int lane = tid & 31;
    const int warp = tid >> 5;

    // ---------- load encoder weights ----------
    load_matrix_interleaved(sm + OFF_W0H, eWhh0, 0);
    load_matrix_interleaved(sm + OFF_W1, eWih1, 0);    // k 0..63  (input = h0)
    load_matrix_interleaved(sm + OFF_W1, eWhh1, 16);   // k 64..127 (input = h1)
    for (int i = tid; i < G_ * IN_; i += THREADS_) {
        int g = i / IN_, k = i - g * IN_;
        sm[OFF_W0X + k * G_ + g] = eWih0[i];
    }
    for (int i = tid; i < G_; i += THREADS_) {
        sm[OFF_B0 + i] = ebih0[i] + ebhh0[i];
        sm[OFF_B1 + i] = ebih1[i] + ebhh1[i];
    }
    for (int i = tid; i < 2 * ROWS_ * H_; i += THREADS_) sm[OFF_HS0 + i] = 0.0f;
    __syncthreads();

    const int rowA = blockIdx.x * ROWS_ + warp * 2;
    const float* srcA = src + (size_t)rowA * S_ * IN_;
    const float* srcB = srcA + S_ * IN_;
    float* hs0A = sm + OFF_HS0 + warp * 2 * H_;
    float* hs0B = hs0A + H_;
    float* hs1A = sm + OFF_HS1 + warp * 2 * H_;
    float* hs1B = hs1A + H_;
    const float4* h0Av = (const float4*)hs0A;
    const float4* h0Bv = (const float4*)hs0B;
    const float4* h1Av = (const float4*)hs1A;
    const float4* h1Bv = (const float4*)hs1B;
    const float4* W0Hv = (const float4*)(sm + OFF_W0H);
    const float4* W1v = (const float4*)(sm + OFF_W1);

    // per-lane bias registers (gate = lane + 32*j)
    float b0r[8], b1r[8];
#pragma unroll
    for (int j = 0; j < 8; j++) {
        b0r[j] = sm[OFF_B0 + lane + 32 * j];
        b1r[j] = sm[OFF_B1 + lane + 32 * j];
    }

    // c-state in registers: (layer, row, unit) with unit0 = lane, unit1 = lane+32
    float c0A0 = 0.f, c0A1 = 0.f, c0B0 = 0.f, c0B1 = 0.f;
    float c1A0 = 0.f, c1A1 = 0.f, c1B0 = 0.f, c1B1 = 0.f;

    float xa[IN_], xb[IN_];
#pragma unroll
    for (int k = 0; k < IN_; k++) {
        xa[k] = __ldg(srcA + k);
        xb[k] = __ldg(srcB + k);
    }

    float a0[8], a1[8];

    // ================= encoder =================
    for (int t = 0; t < S_; t++) {
        // prefetch next x
        float xna[IN_], xnb[IN_];
        if (t + 1 < S_) {
#pragma unroll
            for (int k = 0; k < IN_; k++) {
                xna[k] = __ldg(srcA + (t + 1) * IN_ + k);
                xnb[k] = __ldg(srcB + (t + 1) * IN_ + k);
            }
        }

        // ---- layer 0: gates = x@Wih0^T + h0@Whh0^T + b ----
#pragma unroll
        for (int j = 0; j < 8; j++) { a0[j] = b0r[j]; a1[j] = b0r[j]; }
#pragma unroll
        for (int k = 0; k < IN_; k++) {
#pragma unroll
            for (int j = 0; j < 8; j++) {
                float w = sm[OFF_W0X + k * G_ + lane + 32 * j];
                a0[j] = fmaf(xa[k], w, a0[j]);
                a1[j] = fmaf(xb[k], w, a1[j]);
            }
        }
        gemv_quads<16>(a0, a1, W0Hv, 0, h0Av, h0Bv, lane);
        __syncwarp();
        hs0A[lane]      = cell_update(a0[0], a0[2], a0[4], a0[6], c0A0);
        hs0A[lane + 32] = cell_update(a0[1], a0[3], a0[5], a0[7], c0A1);
        hs0B[lane]      = cell_update(a1[0], a1[2], a1[4], a1[6], c0B0);
        hs0B[lane + 32] = cell_update(a1[1], a1[3], a1[5], a1[7], c0B1);
        __syncwarp();

        // ---- layer 1: gates = h0_new@Wih1^T + h1@Whh1^T + b ----
#pragma unroll
        for (int j = 0; j < 8; j++) { a0[j] = b1r[j]; a1[j] = b1r[j]; }
        gemv_quads<16>(a0, a1, W1v, 0, h0Av, h0Bv, lane);
        gemv_quads<16>(a0, a1, W1v, 16, h1Av, h1Bv, lane);
        __syncwarp();
        hs1A[lane]      = cell_update(a0[0], a0[2], a0[4], a0[6], c1A0);
        hs1A[lane + 32] = cell_update(a0[1], a0[3], a0[5], a0[7], c1A1);
        hs1B[lane]      = cell_update(a1[0], a1[2], a1[4], a1[6], c1B0);
        hs1B[lane + 32] = cell_update(a1[1], a1[3], a1[5], a1[7], c1B1);
        __syncwarp();

        if (t + 1 < S_) {
#pragma unroll
            for (int k = 0; k < IN_; k++) { xa[k] = xna[k]; xb[k] = xnb[k]; }
        }
    }

    // ---------- swap to decoder weights ----------
    __syncthreads();
    load_matrix_interleaved(sm + OFF_W0H, dWhh0, 0);
    load_matrix_interleaved(sm + OFF_W1, dWih1, 0);
    load_matrix_interleaved(sm + OFF_W1, dWhh1, 16);
    for (int i = tid; i < G_; i += THREADS_) {
        sm[OFF_W0X + i] = dWih0[i];  // (4H, 1) -> vector of 256
        sm[OFF_B0 + i] = dbih0[i] + dbhh0[i];
        sm[OFF_B1 + i] = dbih1[i] + dbhh1[i];
    }
    for (int i = tid; i < H_; i += THREADS_) sm[OFF_FCW + i] = fcW[i];
    __syncthreads();

#pragma unroll
    for (int j = 0; j < 8; j++) {
        b0r[j] = sm[OFF_B0 + lane + 32 * j];
        b1r[j] = sm[OFF_B1 + lane + 32 * j];
    }
    const float fcb_r = __ldg(fcb);
    const float fw0 = sm[OFF_FCW + lane];
    const float fw1 = sm[OFF_FCW + lane + 32];

    // dec_in0 = src[:, -1, 3]
    float xA = __ldg(srcA + (S_ - 1) * IN_ + 3);
    float xB = __ldg(srcB + (S_ - 1) * IN_ + 3);

    // ================= decoder =================
    for (int t = 0; t < T_; t++) {
        // ---- layer 0: gates = x*Wih0 + h0@Whh0^T + b ----
#pragma unroll
        for (int j = 0; j < 8; j++) {
            float w = sm[OFF_W0X + lane + 32 * j];
            a0[j] = fmaf(xA, w, b0r[j]);
            a1[j] = fmaf(xB, w, b0r[j]);
        }
        gemv_quads<16>(a0, a1, W0Hv, 0, h0Av, h0Bv, lane);
        __syncwarp();
        hs0A[lane]      = cell_update(a0[0], a0[2], a0[4], a0[6], c0A0);
        hs0A[lane + 32] = cell_update(a0[1], a0[3], a0[5], a0[7], c0A1);
        hs0B[lane]      = cell_update(a1[0], a1[2], a1[4], a1[6], c0B0);
        hs0B[lane + 32] = cell_update(a1[1], a1[3], a1[5], a1[7], c0B1);
        __syncwarp();

        // ---- layer 1 ----
#pragma unroll
        for (int j = 0; j < 8; j++) { a0[j] = b1r[j]; a1[j] = b1r[j]; }
        gemv_quads<16>(a0, a1, W1v, 0, h0Av, h0Bv, lane);
        gemv_quads<16>(a0, a1, W1v, 16, h1Av, h1Bv, lane);
        __syncwarp();
        float hA0 = cell_update(a0[0], a0[2], a0[4], a0[6], c1A0);
        float hA1 = cell_update(a0[1], a0[3], a0[5], a0[7], c1A1);
        float hB0 = cell_update(a1[0], a1[2], a1[4], a1[6], c1B0);
        float hB1 = cell_update(a1[1], a1[3], a1[5], a1[7], c1B1);
        hs1A[lane] = hA0;
        hs1A[lane + 32] = hA1;
        hs1B[lane] = hB0;
        hs1B[lane + 32] = hB1;
        __syncwarp();

        // ---- fc head + feedback ----
        float pA = fmaf(hA0, fw0, hA1 * fw1);
        float pB = fmaf(hB0, fw0, hB1 * fw1);
#pragma unroll
        for (int off = 16; off; off >>= 1) {
            pA += __shfl_xor_sync(0xffffffffu, pA, off);
            pB += __shfl_xor_sync(0xffffffffu, pB, off);
        }
        pA += fcb_r;
        pB += fcb_r;
        if (lane == 0) {
            out[(size_t)rowA * T_ + t] = pA;
            out[(size_t)(rowA + 1) * T_ + t] = pB;
        }
        xA = pA;
        xB = pB;
    }
}

extern "C" void kernel_launch(void* const* d_in, const int* in_sizes, int n_in,
                              void* d_out, int out_size) {
    (void)in_sizes; (void)n_in; (void)out_size;
    const float* src   = (const float*)d_in[0];
    const float* eWih0 = (const float*)d_in[1];
    const float* eWhh0 = (const float*)d_in[2];
    const float* ebih0 = (const float*)d_in[3];
    const float* ebhh0 = (const float*)d_in[4];
    const float* eWih1 = (const float*)d_in[5];
    const float* eWhh1 = (const float*)d_in[6];
    const float* ebih1 = (const float*)d_in[7];
    const float* ebhh1 = (const float*)d_in[8];
    const float* dWih0 = (const float*)d_in[9];
    const float* dWhh0 = (const float*)d_in[10];
    const float* dbih0 = (const float*)d_in[11];
    const float* dbhh0 = (const float*)d_in[12];
    const float* dWih1 = (const float*)d_in[13];
    const float* dWhh1 = (const float*)d_in[14];
    const float* dbih1 = (const float*)d_in[15];
    const float* dbhh1 = (const float*)d_in[16];
    const float* fcW   = (const float*)d_in[17];
    const float* fcb   = (const float*)d_in[18];
    float* out = (float*)d_out;

    cudaFuncSetAttribute(seq2seq_kernel, cudaFuncAttributeMaxDynamicSharedMemorySize, SMEM_BYTES);
    seq2seq_kernel<<<B_ / ROWS_, THREADS_, SMEM_BYTES>>>(
        src, eWih0, eWhh0, ebih0, ebhh0, eWih1, eWhh1, ebih1, ebhh1,
        dWih0, dWhh0, dbih0, dbhh0, dWih1, dWhh1, dbih1, dbhh1,
        fcW, fcb, out);
}

// round 2
// speedup vs baseline: 1.0007x; 1.0007x over previous
#include <cuda_runtime.h>
#include <math.h>

#define B_ 16384
#define S_ 336
#define T_ 48
#define IN_ 5
#define H_ 64
#define G_ 256          // 4*H
#define ROWS_ 16        // batch rows per CTA
#define THREADS_ 256    // 8 warps, 2 rows per warp

// SMEM layout in floats
#define OFF_W1   0          // 32768 floats: [32 quads][256 gates][4]  (Wih1 | Whh1 concat, k-interleaved)
#define OFF_W0H  32768      // 16384 floats: [16 quads][256][4]        (Whh0, k-interleaved)
#define OFF_W0X  49152      // 1280 floats: enc [5][256]; dec uses first 256 as vector
#define OFF_B0   50432      // 256: bih0+bhh0
#define OFF_B1   50688      // 256: bih1+bhh1
#define OFF_FCW  50944      // 64
#define OFF_HS0  51008      // 16*64 h of layer0
#define OFF_HS1  52032      // 16*64 h of layer1
#define SMEM_FLOATS 53056
#define SMEM_BYTES (SMEM_FLOATS * 4)

__device__ __forceinline__ float sigf(float x) { return 1.0f / (1.0f + __expf(-x)); }

__device__ __forceinline__ float cell_update(float gi, float gf, float gg, float go, float& c) {
    float i = sigf(gi), f = sigf(gf), g = tanhf(gg), o = sigf(go);
    c = f * c + i * g;
    return o * tanhf(c);
}

// W: [256][64] row-major (gate-major). Store k-interleaved-by-4:
// dst[(qoff + k/4)*1024 + g*4 + (k%4)]
__device__ __forceinline__ void load_matrix_interleaved(float* dst, const float* __restrict__ W, int qoff) {
    for (int i = threadIdx.x; i < G_ * H_; i += THREADS_) {
        int g = i >> 6, k = i & 63;
        dst[(qoff + (k >> 2)) * 1024 + (g << 2) + (k & 3)] = W[i];
    }
}

// Accumulate NQ k-quads: a[j] += sum_k h[k] * W[g=lane+32j][k]
template <int NQ>
__device__ __forceinline__ void gemv_quads(float* a0, float* a1, const float4* __restrict__ Wv,
                                           int qbase, const float4* hA, const float4* hB, int lane) {
#pragma unroll 4
    for (int q = 0; q < NQ; q++) {
        float4 ha = hA[q];
        float4 hb = hB[q];
        const float4* wrow = Wv + (qbase + q) * 256 + lane;
#pragma unroll
        for (int j = 0; j < 8; j++) {
            float4 w = wrow[32 * j];
            a0[j] = fmaf(ha.x, w.x, a0[j]);
            a0[j] = fmaf(ha.y, w.y, a0[j]);
            a0[j] = fmaf(ha.z, w.z, a0[j]);
            a0[j] = fmaf(ha.w, w.w, a0[j]);
            a1[j] = fmaf(hb.x, w.x, a1[j]);
            a1[j] = fmaf(hb.y, w.y, a1[j]);
            a1[j] = fmaf(hb.z, w.z, a1[j]);
            a1[j] = fmaf(hb.w, w.w, a1[j]);
        }
    }
}

__global__ void __launch_bounds__(THREADS_, 1)
seq2seq_kernel(const float* __restrict__ src,
               const float* __restrict__ eWih0, const float* __restrict__ eWhh0,
               const float* __restrict__ ebih0, const float* __restrict__ ebhh0,
               const float* __restrict__ eWih1, const float* __restrict__ eWhh1,
               const float* __restrict__ ebih1, const float* __restrict__ ebhh1,
               const float* __restrict__ dWih0, const float* __restrict__ dWhh0,
               const float* __restrict__ dbih0, const float* __restrict__ dbhh0,
               const float* __restrict__ dWih1, const float* __restrict__ dWhh1,
               const float* __restrict__ dbih1, const float* __restrict__ dbhh1,
               const float* __restrict__ fcW, const float* __restrict__ fcb,
               float* __restrict__ out) {
    extern __shared__ float sm[];
    const int tid = threadIdx.x;
    const int lane = tid & 31;
    const int warp = tid >> 5;

    // ---------- load encoder weights ----------
    load_matrix_interleaved(sm + OFF_W0H, eWhh0, 0);
    load_matrix_interleaved(sm + OFF_W1, eWih1, 0);    // k 0..63  (input = h0)
    load_matrix_interleaved(sm + OFF_W1, eWhh1, 16);   // k 64..127 (input = h1)
    for (int i = tid; i < G_ * IN_; i += THREADS_) {
        int g = i / IN_, k = i - g * IN_;
        sm[OFF_W0X + k * G_ + g] = eWih0[i];
    }
    for (int i = tid; i < G_; i += THREADS_) {
        sm[OFF_B0 + i] = ebih0[i] + ebhh0[i];
        sm[OFF_B1 + i] = ebih1[i] + ebhh1[i];
    }
    for (int i = tid; i < 2 * ROWS_ * H_; i += THREADS_) sm[OFF_HS0 + i] = 0.0f;
    __syncthreads();

    const int rowA = blockIdx.x * ROWS_ + warp * 2;
    const float* srcA = src + (size_t)rowA * S_ * IN_;
    const float* srcB = srcA + S_ * IN_;
    float* hs0A = sm + OFF_HS0 + warp * 2 * H_;
    float* hs0B = hs0A + H_;
    float* hs1A = sm + OFF_HS1 + warp * 2 * H_;
    float* hs1B = hs1A + H_;
    const float4* h0Av = (const float4*)hs0A;
    const float4* h0Bv = (const float4*)hs0B;
    const float4* h1Av = (const float4*)hs1A;
    const float4* h1Bv = (const float4*)hs1B;
    const float4* W0Hv = (const float4*)(sm + OFF_W0H);
    const float4* W1v = (const float4*)(sm + OFF_W1);

    // per-lane bias registers (gate = lane + 32*j)
    float b0r[8], b1r[8];
#pragma unroll
    for (int j = 0; j < 8; j++) {
        b0r[j] = sm[OFF_B0 + lane + 32 * j];
        b1r[j] = sm[OFF_B1 + lane + 32 * j];
    }

    // c-state in registers: (layer, row, unit) with unit0 = lane, unit1 = lane+32
    float c0A0 = 0.f, c0A1 = 0.f, c0B0 = 0.f, c0B1 = 0.f;
    float c1A0 = 0.f, c1A1 = 0.f, c1B0 = 0.f, c1B1 = 0.f;

    float xa[IN_], xb[IN_];
#pragma unroll
    for (int k = 0; k < IN_; k++) {
        xa[k] = __ldg(srcA + k);
        xb[k] = __ldg(srcB + k);
    }

    float a0[8], a1[8];

    // ================= encoder =================
    for (int t = 0; t < S_; t++) {
        // prefetch next x
        float xna[IN_], xnb[IN_];
        if (t + 1 < S_) {
#pragma unroll
            for (int k = 0; k < IN_; k++) {
                xna[k] = __ldg(srcA + (t + 1) * IN_ + k);
                xnb[k] = __ldg(srcB + (t + 1) * IN_ + k);
            }
        }

        // ---- layer 0: gates = x@Wih0^T + h0@Whh0^T + b ----
#pragma unroll
        for (int j = 0; j < 8; j++) { a0[j] = b0r[j]; a1[j] = b0r[j]; }
#pragma unroll
        for (int k = 0; k < IN_; k++) {
#pragma unroll
            for (int j = 0; j < 8; j++) {
                float w = sm[OFF_W0X + k * G_ + lane + 32 * j];
                a0[j] = fmaf(xa[k], w, a0[j]);
                a1[j] = fmaf(xb[k], w, a1[j]);
            }
        }
        gemv_quads<16>(a0, a1, W0Hv, 0, h0Av, h0Bv, lane);
        __syncwarp();
        hs0A[lane]      = cell_update(a0[0], a0[2], a0[4], a0[6], c0A0);
        hs0A[lane + 32] = cell_update(a0[1], a0[3], a0[5], a0[7], c0A1);
        hs0B[lane]      = cell_update(a1[0], a1[2], a1[4], a1[6], c0B0);
        hs0B[lane + 32] = cell_update(a1[1], a1[3], a1[5], a1[7], c0B1);
        __syncwarp();

        // ---- layer 1: gates = h0_new@Wih1^T + h1@Whh1^T + b ----
#pragma unroll
        for (int j = 0; j < 8; j++) { a0[j] = b1r[j]; a1[j] = b1r[j]; }
        gemv_quads<16>(a0, a1, W1v, 0, h0Av, h0Bv, lane);
        gemv_quads<16>(a0, a1, W1v, 16, h1Av, h1Bv, lane);
        __syncwarp();
        hs1A[lane]      = cell_update(a0[0], a0[2], a0[4], a0[6], c1A0);
        hs1A[lane + 32] = cell_update(a0[1], a0[3], a0[5], a0[7], c1A1);
        hs1B[lane]      = cell_update(a1[0], a1[2], a1[4], a1[6], c1B0);
        hs1B[lane + 32] = cell_update(a1[1], a1[3], a1[5], a1[7], c1B1);
        __syncwarp();

        if (t + 1 < S_) {
#pragma unroll
            for (int k = 0; k < IN_; k++) { xa[k] = xna[k]; xb[k] = xnb[k]; }
        }
    }

    // ---------- swap to decoder weights ----------
    __syncthreads();
    load_matrix_interleaved(sm + OFF_W0H, dWhh0, 0);
    load_matrix_interleaved(sm + OFF_W1, dWih1, 0);
    load_matrix_interleaved(sm + OFF_W1, dWhh1, 16);
    for (int i = tid; i < G_; i += THREADS_) {
        sm[OFF_W0X + i] = dWih0[i];  // (4H, 1) -> vector of 256
        sm[OFF_B0 + i] = dbih0[i] + dbhh0[i];
        sm[OFF_B1 + i] = dbih1[i] + dbhh1[i];
    }
    for (int i = tid; i < H_; i += THREADS_) sm[OFF_FCW + i] = fcW[i];
    __syncthreads();

#pragma unroll
    for (int j = 0; j < 8; j++) {
        b0r[j] = sm[OFF_B0 + lane + 32 * j];
        b1r[j] = sm[OFF_B1 + lane + 32 * j];
    }
    const float fcb_r = __ldg(fcb);
    const float fw0 = sm[OFF_FCW + lane];
    const float fw1 = sm[OFF_FCW + lane + 32];

    // dec_in0 = src[:, -1, 3]
    float xA = __ldg(srcA + (S_ - 1) * IN_ + 3);
    float xB = __ldg(srcB + (S_ - 1) * IN_ + 3);

    // ================= decoder =================
    for (int t = 0; t < T_; t++) {
        // ---- layer 0: gates = x*Wih0 + h0@Whh0^T + b ----
#pragma unroll
        for (int j = 0; j < 8; j++) {
            float w = sm[OFF_W0X + lane + 32 * j];
            a0[j] = fmaf(xA, w, b0r[j]);
            a1[j] = fmaf(xB, w, b0r[j]);
        }
        gemv_quads<16>(a0, a1, W0Hv, 0, h0Av, h0Bv, lane);
        __syncwarp();
        hs0A[lane]      = cell_update(a0[0], a0[2], a0[4], a0[6], c0A0);
        hs0A[lane + 32] = cell_update(a0[1], a0[3], a0[5], a0[7], c0A1);
        hs0B[lane]      = cell_update(a1[0], a1[2], a1[4], a1[6], c0B0);
        hs0B[lane + 32] = cell_update(a1[1], a1[3], a1[5], a1[7], c0B1);
        __syncwarp();

        // ---- layer 1 ----
#pragma unroll
        for (int j = 0; j < 8; j++) { a0[j] = b1r[j]; a1[j] = b1r[j]; }
        gemv_quads<16>(a0, a1, W1v, 0, h0Av, h0Bv, lane);
        gemv_quads<16>(a0, a1, W1v, 16, h1Av, h1Bv, lane);
        __syncwarp();
        float hA0 = cell_update(a0[0], a0[2], a0[4], a0[6], c1A0);
        float hA1 = cell_update(a0[1], a0[3], a0[5], a0[7], c1A1);
        float hB0 = cell_update(a1[0], a1[2], a1[4], a1[6], c1B0);
        float hB1 = cell_update(a1[1], a1[3], a1[5], a1[7], c1B1);
        hs1A[lane] = hA0;
        hs1A[lane + 32] = hA1;
        hs1B[lane] = hB0;
        hs1B[lane + 32] = hB1;
        __syncwarp();

        // ---- fc head + feedback ----
        float pA = fmaf(hA0, fw0, hA1 * fw1);
        float pB = fmaf(hB0, fw0, hB1 * fw1);
#pragma unroll
        for (int off = 16; off; off >>= 1) {
            pA += __shfl_xor_sync(0xffffffffu, pA, off);
            pB += __shfl_xor_sync(0xffffffffu, pB, off);
        }
        pA += fcb_r;
        pB += fcb_r;
        if (lane == 0) {
            out[(size_t)rowA * T_ + t] = pA;
            out[(size_t)(rowA + 1) * T_ + t] = pB;
        }
        xA = pA;
        xB = pB;
    }
}

extern "C" void kernel_launch(void* const* d_in, const int* in_sizes, int n_in,
                              void* d_out, int out_size) {
    (void)in_sizes; (void)n_in; (void)out_size;
    const float* src   = (const float*)d_in[0];
    const float* eWih0 = (const float*)d_in[1];
    const float* eWhh0 = (const float*)d_in[2];
    const float* ebih0 = (const float*)d_in[3];
    const float* ebhh0 = (const float*)d_in[4];
    const float* eWih1 = (const float*)d_in[5];
    const float* eWhh1 = (const float*)d_in[6];
    const float* ebih1 = (const float*)d_in[7];
    const float* ebhh1 = (const float*)d_in[8];
    const float* dWih0 = (const float*)d_in[9];
    const float* dWhh0 = (const float*)d_in[10];
    const float* dbih0 = (const float*)d_in[11];
    const float* dbhh0 = (const float*)d_in[12];
    const float* dWih1 = (const float*)d_in[13];
    const float* dWhh1 = (const float*)d_in[14];
    const float* dbih1 = (const float*)d_in[15];
    const float* dbhh1 = (const float*)d_in[16];
    const float* fcW   = (const float*)d_in[17];
    const float* fcb   = (const float*)d_in[18];
    float* out = (float*)d_out;

    cudaFuncSetAttribute(seq2seq_kernel, cudaFuncAttributeMaxDynamicSharedMemorySize, SMEM_BYTES);
    seq2seq_kernel<<<B_ / ROWS_, THREADS_, SMEM_BYTES>>>(
        src, eWih0, eWhh0, ebih0, ebhh0, eWih1, eWhh1, ebih1, ebhh1,
        dWih0, dWhh0, dbih0, dbhh0, dWih1, dWhh1, dbih1, dbhh1,
        fcW, fcb, out);
}

// round 4
// speedup vs baseline: 6.6234x; 6.6190x over previous
#include <cuda_runtime.h>
#include <cuda_fp16.h>
#include <cstdint>

#define B_ 16384
#define S_ 336
#define T_ 48
#define MROWS_ 128
#define NCTA_ (B_ / MROWS_)
#define THREADS_ 256

// smem byte offsets
#define H0A_ 0
#define H0B_ 16384
#define H1A_ 32768
#define H1B_ 49152
#define WHH0_ 65536
#define W1A_ 98304
#define W1B_ 131072
#define W0X_ 163840
#define XT_ 176128
#define FCW_ 182272
#define SMEM_BYTES 182784

#define L2E 1.4426950408889634f

__device__ __forceinline__ uint32_t smem_u32(const void* p) {
    uint32_t a;
    asm("{ .reg .u64 t; cvta.to.shared.u64 t, %1; cvt.u32.u64 %0, t; }" : "=r"(a) : "l"(p));
    return a;
}
__device__ __forceinline__ void sts32(uint32_t a, uint32_t v) {
    asm volatile("st.shared.u32 [%0], %1;" :: "r"(a), "r"(v) : "memory");
}
__device__ __forceinline__ uint4 lds128(uint32_t a) {
    uint4 v;
    asm volatile("ld.shared.v4.u32 {%0,%1,%2,%3}, [%4];" : "=r"(v.x), "=r"(v.y), "=r"(v.z), "=r"(v.w) : "r"(a));
    return v;
}
#define LDSM4(r0, r1, r2, r3, addr) \
    asm volatile("ldmatrix.sync.aligned.m8n8.x4.shared.b16 {%0,%1,%2,%3}, [%4];" \
        : "=r"(r0), "=r"(r1), "=r"(r2), "=r"(r3) : "r"(addr))

__device__ __forceinline__ void mma16816(float* d, uint32_t a0, uint32_t a1, uint32_t a2, uint32_t a3,
                                         uint32_t b0, uint32_t b1) {
    asm volatile(
        "mma.sync.aligned.m16n8k16.row.col.f32.f16.f16.f32 "
        "{%0,%1,%2,%3},{%4,%5,%6,%7},{%8,%9},{%0,%1,%2,%3};"
        : "+f"(d[0]), "+f"(d[1]), "+f"(d[2]), "+f"(d[3])
        : "r"(a0), "r"(a1), "r"(a2), "r"(a3), "r"(b0), "r"(b1));
}

__device__ __forceinline__ float ex2f(float x) { float y; asm("ex2.approx.ftz.f32 %0,%1;" : "=f"(y) : "f"(x)); return y; }
__device__ __forceinline__ float rcpf(float x) { float y; asm("rcp.approx.ftz.f32 %0,%1;" : "=f"(y) : "f"(x)); return y; }
__device__ __forceinline__ float sigv(float x) { return rcpf(1.0f + ex2f(-L2E * x)); }
__device__ __forceinline__ float tanv(float x) { return fmaf(-2.0f, rcpf(1.0f + ex2f((2.0f * L2E) * x)), 1.0f); }

// permuted gate row: smem row n -> source gate ((n>>3)&3)*64 + (n>>5)*8 + (n&7)
__device__ __forceinline__ int perm_gate(int n) {
    return ((n >> 3) & 3) * 64 + (n >> 5) * 8 + (n & 7);
}

// [256][64] fp16 tile, 128B rows, chunk swizzle c^(row&7), from fp32 row-major [256][64]
__device__ __forceinline__ void fill_wtile(uint32_t dst, const float* __restrict__ W) {
    for (int i = threadIdx.x; i < 256 * 32; i += THREADS_) {
        int n = i >> 5, p = i & 31;
        int gate = perm_gate(n);
        float2 v = *(const float2*)(W + gate * 64 + 2 * p);
        __half2 h = __floats2half2_rn(v.x, v.y);
        int chunk = p >> 2;
        sts32(dst + n * 128 + ((chunk ^ (n & 7)) << 4) + ((p & 3) << 2), *(uint32_t*)&h);
    }
}
// [256][16] fp16 tile, 48B row stride (no swizzle), first `incols` cols from W [256][incols]
__device__ __forceinline__ void fill_w0x(uint32_t dst, const float* __restrict__ W, int incols) {
    for (int i = threadIdx.x; i < 256 * 8; i += THREADS_) {
        int n = i >> 3, p = i & 7;
        int gate = perm_gate(n);
        int k0 = 2 * p, k1 = 2 * p + 1;
        float v0 = (k0 < incols) ? W[gate * incols + k0] : 0.0f;
        float v1 = (k1 < incols) ? W[gate * incols + k1] : 0.0f;
        __half2 h = __floats2half2_rn(v0, v1);
        sts32(dst + n * 48 + p * 4, *(uint32_t*)&h);
    }
}

__device__ __forceinline__ void load_bias(float* b, const float* __restrict__ bih,
                                          const float* __restrict__ bhh, int uA) {
#pragma unroll
    for (int g = 0; g < 4; g++) {
        int i = g * 64 + uA;
        b[2 * g] = __ldg(bih + i) + __ldg(bhh + i);
        b[2 * g + 1] = __ldg(bih + i + 1) + __ldg(bhh + i + 1);
    }
}

// One LSTM layer for 128 rows x 64 units.
// A-sources: a1base = h tile [128][64] (4 ksteps), a2base = XPART ? x tile [128][16] (1 kstep)
//            : second h tile (4 ksteps). Weights w1base/w2base match.
template <bool XPART>
__device__ __forceinline__ void lstm_phase(uint32_t a1base, uint32_t a2base,
                                           uint32_t w1base, uint32_t w2base,
                                           uint32_t hwr, const float* bias, float* cst,
                                           int warp, int lane) {
    const int mat = lane >> 3;
    const int brow = 32 * warp + 8 * (mat >> 1) + (lane & 7);
    const int bxor = lane & 7;
    const int bch = mat & 1;
    const int rowp = lane & 15;
    const int kh = lane >> 4;

    // B fragments -> registers
    uint32_t b1r[32];
#pragma unroll
    for (int ks = 0; ks < 4; ks++) {
        uint32_t aA = w1base + brow * 128 + (((2 * ks + bch) ^ bxor) << 4);
        LDSM4(b1r[ks * 8 + 0], b1r[ks * 8 + 1], b1r[ks * 8 + 2], b1r[ks * 8 + 3], aA);
        uint32_t aB = w1base + (brow + 16) * 128 + (((2 * ks + bch) ^ bxor) << 4);
        LDSM4(b1r[ks * 8 + 4], b1r[ks * 8 + 5], b1r[ks * 8 + 6], b1r[ks * 8 + 7], aB);
    }
    uint32_t b2r[32];
    if (XPART) {
        uint32_t aA = w2base + brow * 48 + bch * 16;
        LDSM4(b2r[0], b2r[1], b2r[2], b2r[3], aA);
        uint32_t aB = w2base + (brow + 16) * 48 + bch * 16;
        LDSM4(b2r[4], b2r[5], b2r[6], b2r[7], aB);
    } else {
#pragma unroll
        for (int ks = 0; ks < 4; ks++) {
            uint32_t aA = w2base + brow * 128 + (((2 * ks + bch) ^ bxor) << 4);
            LDSM4(b2r[ks * 8 + 0], b2r[ks * 8 + 1], b2r[ks * 8 + 2], b2r[ks * 8 + 3], aA);
            uint32_t aB = w2base + (brow + 16) * 128 + (((2 * ks + bch) ^ bxor) << 4);
            LDSM4(b2r[ks * 8 + 4], b2r[ks * 8 + 5], b2r[ks * 8 + 6], b2r[ks * 8 + 7], aB);
        }
    }

#pragma unroll
    for (int m = 0; m < 8; m++) {
        float acc[4][4];
#pragma unroll
        for (int g = 0; g < 4; g++) {
            acc[g][0] = bias[2 * g];
            acc[g][1] = bias[2 * g + 1];
            acc[g][2] = bias[2 * g];
            acc[g][3] = bias[2 * g + 1];
        }
        uint32_t a0, a1, a2, a3;
#pragma unroll
        for (int ks = 0; ks < 4; ks++) {
            uint32_t aa = a1base + (m * 16 + rowp) * 128 + (((2 * ks + kh) ^ (rowp & 7)) << 4);
            LDSM4(a0, a1, a2, a3, aa);
#pragma unroll
            for (int j = 0; j < 4; j++)
                mma16816(acc[j], a0, a1, a2, a3, b1r[ks * 8 + j * 2], b1r[ks * 8 + j * 2 + 1]);
        }
        if (XPART) {
            uint32_t aa = a2base + (m * 16 + rowp) * 48 + kh * 16;
            LDSM4(a0, a1, a2, a3, aa);
#pragma unroll
            for (int j = 0; j < 4; j++)
                mma16816(acc[j], a0, a1, a2, a3, b2r[j * 2], b2r[j * 2 + 1]);
        } else {
#pragma unroll
            for (int ks = 0; ks < 4; ks++) {
                uint32_t aa = a2base + (m * 16 + rowp) * 128 + (((2 * ks + kh) ^ (rowp & 7)) << 4);
                LDSM4(a0, a1, a2, a3, aa);
#pragma unroll
                for (int j = 0; j < 4; j++)
                    mma16816(acc[j], a0, a1, a2, a3, b2r[ks * 8 + j * 2], b2r[ks * 8 + j * 2 + 1]);
            }
        }
        // epilogue: 4 cells = {row, row+8} x {uA, uA+1}
        float h[4];
#pragma unroll
        for (int d = 0; d < 4; d++) {
            float i_ = sigv(acc[0][d]);
            float f_ = sigv(acc[1][d]);
            float g_ = tanv(acc[2][d]);
            float o_ = sigv(acc[3][d]);
            float c = fmaf(f_, cst[m * 4 + d], i_ * g_);
            cst[m * 4 + d] = c;
            h[d] = o_ * tanv(c);
        }
        uint32_t cx = ((uint32_t)warp ^ (uint32_t)((lane >> 2) & 7)) << 4;
        uint32_t ba = hwr + (m * 16 + (lane >> 2)) * 128 + cx + (lane & 3) * 4;
        __half2 p1 = __floats2half2_rn(h[0], h[1]);
        sts32(ba, *(uint32_t*)&p1);
        __half2 p2 = __floats2half2_rn(h[2], h[3]);
        sts32(ba + 8 * 128, *(uint32_t*)&p2);
    }
}

__global__ void __launch_bounds__(THREADS_, 1)
seq2seq_mma(const float* __restrict__ src,
            const float* __restrict__ eWih0, const float* __restrict__ eWhh0,
            const float* __restrict__ ebih0, const float* __restrict__ ebhh0,
            const float* __restrict__ eWih1, const float* __restrict__ eWhh1,
            const float* __restrict__ ebih1, const float* __restrict__ ebhh1,
            const float* __restrict__ dWih0, const float* __restrict__ dWhh0,
            const float* __restrict__ dbih0, const float* __restrict__ dbhh0,
            const float* __restrict__ dWih1, const float* __restrict__ dWhh1,
            const float* __restrict__ dbih1, const float* __restrict__ dbhh1,
            const float* __restrict__ fcW, const float* __restrict__ fcb,
            float* __restrict__ out) {
    extern __shared__ char smc[];
    const uint32_t sb = smem_u32(smc);
    const int tid = threadIdx.x;
    const int lane = tid & 31;
    const int warp = tid >> 5;
    const int row0 = blockIdx.x * MROWS_;

    // zero h buffers + W0X/XT region
    {
        uint4 z = make_uint4(0, 0, 0, 0);
        uint4* p0 = (uint4*)smc;
        for (int i = tid; i < 65536 / 16; i += THREADS_) p0[i] = z;
        uint4* p1 = (uint4*)(smc + W0X_);
        for (int i = tid; i < (SMEM_BYTES - W0X_) / 16; i += THREADS_) p1[i] = z;
    }
    __syncthreads();

    fill_wtile(sb + WHH0_, eWhh0);
    fill_wtile(sb + W1A_, eWih1);
    fill_wtile(sb + W1B_, eWhh1);
    fill_w0x(sb + W0X_, eWih0, 5);

    const float* srcRow = src + (size_t)(row0 + tid) * S_ * 5;
    if (tid < MROWS_) {  // x(0)
        uint32_t xb = sb + XT_ + tid * 48;
        __half2 a01 = __floats2half2_rn(__ldg(srcRow + 0), __ldg(srcRow + 1));
        __half2 a23 = __floats2half2_rn(__ldg(srcRow + 2), __ldg(srcRow + 3));
        __half2 a4z = __floats2half2_rn(__ldg(srcRow + 4), 0.0f);
        sts32(xb, *(uint32_t*)&a01);
        sts32(xb + 4, *(uint32_t*)&a23);
        sts32(xb + 8, *(uint32_t*)&a4z);
    }

    const int uA = 8 * warp + (lane & 3) * 2;
    float b0[8], b1[8];
    load_bias(b0, ebih0, ebhh0, uA);
    load_bias(b1, ebih1, ebhh1, uA);

    float c0[32], c1[32];
#pragma unroll
    for (int j = 0; j < 32; j++) { c0[j] = 0.0f; c1[j] = 0.0f; }

    __syncthreads();

    int p = 0;
    // ================= encoder =================
    for (int t = 0; t < S_; t++) {
        float x0, x1, x2, x3, x4;
        if (tid < MROWS_ && t + 1 < S_) {
            const float* xp = srcRow + (size_t)(t + 1) * 5;
            x0 = __ldg(xp + 0); x1 = __ldg(xp + 1); x2 = __ldg(xp + 2);
            x3 = __ldg(xp + 3); x4 = __ldg(xp + 4);
        }
        const uint32_t h0r = sb + (p ? H0B_ : H0A_), h0w = sb + (p ? H0A_ : H0B_);
        const uint32_t h1r = sb + (p ? H1B_ : H1A_), h1w = sb + (p ? H1A_ : H1B_);

        lstm_phase<true>(h0r, sb + XT_, sb + WHH0_, sb + W0X_, h0w, b0, c0, warp, lane);
        __syncthreads();
        if (tid < MROWS_ && t + 1 < S_) {
            uint32_t xb = sb + XT_ + tid * 48;
            __half2 a01 = __floats2half2_rn(x0, x1);
            __half2 a23 = __floats2half2_rn(x2, x3);
            __half2 a4z = __floats2half2_rn(x4, 0.0f);
            sts32(xb, *(uint32_t*)&a01);
            sts32(xb + 4, *(uint32_t*)&a23);
            sts32(xb + 8, *(uint32_t*)&a4z);
        }
        lstm_phase<false>(h0w, h1r, sb + W1A_, sb + W1B_, h1w, b1, c1, warp, lane);
        __syncthreads();
        p ^= 1;
    }

    // ---------- decoder swap ----------
    fill_wtile(sb + WHH0_, dWhh0);
    fill_wtile(sb + W1A_, dWih1);
    fill_wtile(sb + W1B_, dWhh1);
    fill_w0x(sb + W0X_, dWih0, 1);
    load_bias(b0, dbih0, dbhh0, uA);
    load_bias(b1, dbih1, dbhh1, uA);
    for (int i = tid; i < 64; i += THREADS_) ((float*)(smc + FCW_))[i] = __ldg(fcW + i);
    if (tid < MROWS_) {
        float xd = __ldg(srcRow + (size_t)(S_ - 1) * 5 + 3);
        uint32_t xb = sb + XT_ + tid * 48;
        __half2 a01 = __floats2half2_rn(xd, 0.0f);
        sts32(xb, *(uint32_t*)&a01);
        sts32(xb + 4, 0u);
        sts32(xb + 8, 0u);
    }
    const float fcb_r = __ldg(fcb);
    const float* fcw_sm = (const float*)(smc + FCW_);
    __syncthreads();

    // ================= decoder =================
    for (int t = 0; t < T_; t++) {
        const uint32_t h0r = sb + (p ? H0B_ : H0A_), h0w = sb + (p ? H0A_ : H0B_);
        const uint32_t h1r = sb + (p ? H1B_ : H1A_), h1w = sb + (p ? H1A_ : H1B_);

        lstm_phase<true>(h0r, sb + XT_, sb + WHH0_, sb + W0X_, h0w, b0, c0, warp, lane);
        __syncthreads();
        lstm_phase<false>(h0w, h1r, sb + W1A_, sb + W1B_, h1w, b1, c1, warp, lane);
        __syncthreads();

        if (tid < MROWS_) {
            float acc = fcb_r;
            uint32_t ra = h1w + tid * 128;
#pragma unroll
            for (int c = 0; c < 8; c++) {
                uint4 q = lds128(ra + ((c ^ (tid & 7)) << 4));
                float2 f0 = __half22float2(*(__half2*)&q.x);
                float2 f1 = __half22float2(*(__half2*)&q.y);
                float2 f2 = __half22float2(*(__half2*)&q.z);
                float2 f3 = __half22float2(*(__half2*)&q.w);
                acc = fmaf(f0.x, fcw_sm[c * 8 + 0], acc);
                acc = fmaf(f0.y, fcw_sm[c * 8 + 1], acc);
                acc = fmaf(f1.x, fcw_sm[c * 8 + 2], acc);
                acc = fmaf(f1.y, fcw_sm[c * 8 + 3], acc);
                acc = fmaf(f2.x, fcw_sm[c * 8 + 4], acc);
                acc = fmaf(f2.y, fcw_sm[c * 8 + 5], acc);
                acc = fmaf(f3.x, fcw_sm[c * 8 + 6], acc);
                acc = fmaf(f3.y, fcw_sm[c * 8 + 7], acc);
            }
            out[(size_t)(row0 + tid) * T_ + t] = acc;
            __half2 a01 = __floats2half2_rn(acc, 0.0f);
            sts32(sb + XT_ + tid * 48, *(uint32_t*)&a01);
        }
        __syncthreads();
        p ^= 1;
    }
}

extern "C" void kernel_launch(void* const* d_in, const int* in_sizes, int n_in,
                              void* d_out, int out_size) {
    (void)in_sizes; (void)n_in; (void)out_size;
    cudaFuncSetAttribute(seq2seq_mma, cudaFuncAttributeMaxDynamicSharedMemorySize, SMEM_BYTES);
    seq2seq_mma<<<NCTA_, THREADS_, SMEM_BYTES>>>(
        (const float*)d_in[0],
        (const float*)d_in[1], (const float*)d_in[2], (const float*)d_in[3], (const float*)d_in[4],
        (const float*)d_in[5], (const float*)d_in[6], (const float*)d_in[7], (const float*)d_in[8],
        (const float*)d_in[9], (const float*)d_in[10], (const float*)d_in[11], (const float*)d_in[12],
        (const float*)d_in[13], (const float*)d_in[14], (const float*)d_in[15], (const float*)d_in[16],
        (const float*)d_in[17], (const float*)d_in[18],
        (float*)d_out);
}

// round 5
// speedup vs baseline: 7.9558x; 1.2012x over previous
#include <cuda_runtime.h>
#include <cuda_fp16.h>
#include <cstdint>

#define B_ 16384
#define S_ 336
#define T_ 48
#define MROWS_ 128
#define NCTA_ (B_ / MROWS_)
#define THREADS_ 512

// smem byte offsets
#define H0A_ 0
#define H0B_ 16384
#define H1A_ 32768
#define H1B_ 49152
#define WHH0_ 65536
#define W1A_ 98304
#define W1B_ 131072
#define W0X_ 163840
#define XT_ 176128
#define FCW_ 182272
#define BIAS0_ 182528
#define BIAS1_ 183552
#define SMEM_BYTES 184832

#define L2E 1.4426950408889634f

__device__ __forceinline__ uint32_t smem_u32(const void* p) {
    uint32_t a;
    asm("{ .reg .u64 t; cvta.to.shared.u64 t, %1; cvt.u32.u64 %0, t; }" : "=r"(a) : "l"(p));
    return a;
}
__device__ __forceinline__ void sts32(uint32_t a, uint32_t v) {
    asm volatile("st.shared.u32 [%0], %1;" :: "r"(a), "r"(v) : "memory");
}
__device__ __forceinline__ uint4 lds128(uint32_t a) {
    uint4 v;
    asm volatile("ld.shared.v4.u32 {%0,%1,%2,%3}, [%4];" : "=r"(v.x), "=r"(v.y), "=r"(v.z), "=r"(v.w) : "r"(a));
    return v;
}
#define LDSM4(r0, r1, r2, r3, addr) \
    asm volatile("ldmatrix.sync.aligned.m8n8.x4.shared.b16 {%0,%1,%2,%3}, [%4];" \
        : "=r"(r0), "=r"(r1), "=r"(r2), "=r"(r3) : "r"(addr))

__device__ __forceinline__ void mma16816(float* d, uint32_t a0, uint32_t a1, uint32_t a2, uint32_t a3,
                                         uint32_t b0, uint32_t b1) {
    asm volatile(
        "mma.sync.aligned.m16n8k16.row.col.f32.f16.f16.f32 "
        "{%0,%1,%2,%3},{%4,%5,%6,%7},{%8,%9},{%0,%1,%2,%3};"
        : "+f"(d[0]), "+f"(d[1]), "+f"(d[2]), "+f"(d[3])
        : "r"(a0), "r"(a1), "r"(a2), "r"(a3), "r"(b0), "r"(b1));
}

__device__ __forceinline__ float ex2f(float x) { float y; asm("ex2.approx.ftz.f32 %0,%1;" : "=f"(y) : "f"(x)); return y; }
__device__ __forceinline__ float rcpf(float x) { float y; asm("rcp.approx.ftz.f32 %0,%1;" : "=f"(y) : "f"(x)); return y; }
// exact-ish tanh (for cell output path)
__device__ __forceinline__ float tanv(float x) { return fmaf(-2.0f, rcpf(1.0f + ex2f((2.0f * L2E) * x)), 1.0f); }
// hardware tanh (1 MUFU)
__device__ __forceinline__ float tanh_a(float x) { float y; asm("tanh.approx.f32 %0,%1;" : "=f"(y) : "f"(x)); return y; }
__device__ __forceinline__ float sig_a(float x) { return fmaf(tanh_a(0.5f * x), 0.5f, 0.5f); }

// permuted gate row: smem row n -> source gate ((n>>3)&3)*64 + (n>>5)*8 + (n&7)
__device__ __forceinline__ int perm_gate(int n) {
    return ((n >> 3) & 3) * 64 + (n >> 5) * 8 + (n & 7);
}

// [256][64] fp16 tile, 128B rows, chunk swizzle c^(row&7), from fp32 row-major [256][64]
__device__ __forceinline__ void fill_wtile(uint32_t dst, const float* __restrict__ W) {
    for (int i = threadIdx.x; i < 256 * 32; i += THREADS_) {
        int n = i >> 5, p = i & 31;
        int gate = perm_gate(n);
        float2 v = *(const float2*)(W + gate * 64 + 2 * p);
        __half2 h = __floats2half2_rn(v.x, v.y);
        int chunk = p >> 2;
        sts32(dst + n * 128 + ((chunk ^ (n & 7)) << 4) + ((p & 3) << 2), *(uint32_t*)&h);
    }
}
// [256][16] fp16 tile, 48B row stride (no swizzle), first `incols` cols from W [256][incols]
__device__ __forceinline__ void fill_w0x(uint32_t dst, const float* __restrict__ W, int incols) {
    for (int i = threadIdx.x; i < 256 * 8; i += THREADS_) {
        int n = i >> 3, p = i & 7;
        int gate = perm_gate(n);
        int k0 = 2 * p, k1 = 2 * p + 1;
        float v0 = (k0 < incols) ? W[gate * incols + k0] : 0.0f;
        float v1 = (k1 < incols) ? W[gate * incols + k1] : 0.0f;
        __half2 h = __floats2half2_rn(v0, v1);
        sts32(dst + n * 48 + p * 4, *(uint32_t*)&h);
    }
}

// One LSTM layer slice: 64 rows (rowgroup rg) x 8 units (unitgroup ng).
template <bool XPART>
__device__ __forceinline__ void lstm_phase(uint32_t a1base, uint32_t a2base,
                                           uint32_t w1base, uint32_t w2base,
                                           uint32_t hwr, const float* biasp, float* cst,
                                           int rg, int ng, int lane) {
    const int mat = lane >> 3;
    const int brow = 32 * ng + 8 * (mat >> 1) + (lane & 7);
    const int bxor = lane & 7;
    const int bch = mat & 1;
    const int rowp = lane & 15;
    const int kh = lane >> 4;
    const int uA = 8 * ng + (lane & 3) * 2;

    // B fragments -> registers
    uint32_t b1r[32];
#pragma unroll
    for (int ks = 0; ks < 4; ks++) {
        uint32_t aA = w1base + brow * 128 + (((2 * ks + bch) ^ bxor) << 4);
        LDSM4(b1r[ks * 8 + 0], b1r[ks * 8 + 1], b1r[ks * 8 + 2], b1r[ks * 8 + 3], aA);
        uint32_t aB = w1base + (brow + 16) * 128 + (((2 * ks + bch) ^ bxor) << 4);
        LDSM4(b1r[ks * 8 + 4], b1r[ks * 8 + 5], b1r[ks * 8 + 6], b1r[ks * 8 + 7], aB);
    }
    uint32_t b2r[XPART ? 8 : 32];
    if (XPART) {
        uint32_t aA = w2base + brow * 48 + bch * 16;
        LDSM4(b2r[0], b2r[1], b2r[2], b2r[3], aA);
        uint32_t aB = w2base + (brow + 16) * 48 + bch * 16;
        LDSM4(b2r[4], b2r[5], b2r[6], b2r[7], aB);
    } else {
#pragma unroll
        for (int ks = 0; ks < 4; ks++) {
            uint32_t aA = w2base + brow * 128 + (((2 * ks + bch) ^ bxor) << 4);
            LDSM4(b2r[ks * 8 + 0], b2r[ks * 8 + 1], b2r[ks * 8 + 2], b2r[ks * 8 + 3], aA);
            uint32_t aB = w2base + (brow + 16) * 128 + (((2 * ks + bch) ^ bxor) << 4);
            LDSM4(b2r[ks * 8 + 4], b2r[ks * 8 + 5], b2r[ks * 8 + 6], b2r[ks * 8 + 7], aB);
        }
    }

#pragma unroll
    for (int mi = 0; mi < 4; mi++) {
        const int rowbase = rg * 64 + mi * 16;
        float acc[4][4];
#pragma unroll
        for (int g = 0; g < 4; g++) {
            float2 bv = *(const float2*)(biasp + g * 64 + uA);
            acc[g][0] = bv.x; acc[g][1] = bv.y;
            acc[g][2] = bv.x; acc[g][3] = bv.y;
        }
        uint32_t a0, a1, a2, a3;
#pragma unroll
        for (int ks = 0; ks < 4; ks++) {
            uint32_t aa = a1base + (rowbase + rowp) * 128 + (((2 * ks + kh) ^ (rowp & 7)) << 4);
            LDSM4(a0, a1, a2, a3, aa);
#pragma unroll
            for (int j = 0; j < 4; j++)
                mma16816(acc[j], a0, a1, a2, a3, b1r[ks * 8 + j * 2], b1r[ks * 8 + j * 2 + 1]);
        }
        if (XPART) {
            uint32_t aa = a2base + (rowbase + rowp) * 48 + kh * 16;
            LDSM4(a0, a1, a2, a3, aa);
#pragma unroll
            for (int j = 0; j < 4; j++)
                mma16816(acc[j], a0, a1, a2, a3, b2r[j * 2], b2r[j * 2 + 1]);
        } else {
#pragma unroll
            for (int ks = 0; ks < 4; ks++) {
                uint32_t aa = a2base + (rowbase + rowp) * 128 + (((2 * ks + kh) ^ (rowp & 7)) << 4);
                LDSM4(a0, a1, a2, a3, aa);
#pragma unroll
                for (int j = 0; j < 4; j++)
                    mma16816(acc[j], a0, a1, a2, a3, b2r[ks * 8 + j * 2], b2r[ks * 8 + j * 2 + 1]);
            }
        }
        // epilogue: 4 cells = {row, row+8} x {uA, uA+1}
        float h[4];
#pragma unroll
        for (int d = 0; d < 4; d++) {
            float i_ = sig_a(acc[0][d]);
            float f_ = sig_a(acc[1][d]);
            float g_ = tanh_a(acc[2][d]);
            float o_ = sig_a(acc[3][d]);
            float c = fmaf(f_, cst[mi * 4 + d], i_ * g_);
            cst[mi * 4 + d] = c;
            h[d] = o_ * tanv(c);
        }
        uint32_t cx = ((uint32_t)(ng ^ ((lane >> 2) & 7))) << 4;
        uint32_t ba = hwr + (rowbase + (lane >> 2)) * 128 + cx + (lane & 3) * 4;
        __half2 p1 = __floats2half2_rn(h[0], h[1]);
        sts32(ba, *(uint32_t*)&p1);
        __half2 p2 = __floats2half2_rn(h[2], h[3]);
        sts32(ba + 8 * 128, *(uint32_t*)&p2);
    }
}

__global__ void __launch_bounds__(THREADS_, 1)
seq2seq_mma(const float* __restrict__ src,
            const float* __restrict__ eWih0, const float* __restrict__ eWhh0,
            const float* __restrict__ ebih0, const float* __restrict__ ebhh0,
            const float* __restrict__ eWih1, const float* __restrict__ eWhh1,
            const float* __restrict__ ebih1, const float* __restrict__ ebhh1,
            const float* __restrict__ dWih0, const float* __restrict__ dWhh0,
            const float* __restrict__ dbih0, const float* __restrict__ dbhh0,
            const float* __restrict__ dWih1, const float* __restrict__ dWhh1,
            const float* __restrict__ dbih1, const float* __restrict__ dbhh1,
            const float* __restrict__ fcW, const float* __restrict__ fcb,
            float* __restrict__ out) {
    extern __shared__ char smc[];
    const uint32_t sb = smem_u32(smc);
    const int tid = threadIdx.x;
    const int lane = tid & 31;
    const int warp = tid >> 5;
    const int rg = warp >> 3;
    const int ng = warp & 7;
    const int row0 = blockIdx.x * MROWS_;

    // zero h buffers + W0X/XT region
    {
        uint4 z = make_uint4(0, 0, 0, 0);
        uint4* p0 = (uint4*)smc;
        for (int i = tid; i < 65536 / 16; i += THREADS_) p0[i] = z;
        uint4* p1 = (uint4*)(smc + W0X_);
        for (int i = tid; i < (SMEM_BYTES - W0X_) / 16; i += THREADS_) p1[i] = z;
    }
    __syncthreads();

    fill_wtile(sb + WHH0_, eWhh0);
    fill_wtile(sb + W1A_, eWih1);
    fill_wtile(sb + W1B_, eWhh1);
    fill_w0x(sb + W0X_, eWih0, 5);
    for (int i = tid; i < 256; i += THREADS_) {
        ((float*)(smc + BIAS0_))[i] = __ldg(ebih0 + i) + __ldg(ebhh0 + i);
        ((float*)(smc + BIAS1_))[i] = __ldg(ebih1 + i) + __ldg(ebhh1 + i);
    }

    const float* srcRow = src + (size_t)(row0 + tid) * S_ * 5;
    if (tid < MROWS_) {  // x(0)
        uint32_t xb = sb + XT_ + tid * 48;
        __half2 a01 = __floats2half2_rn(__ldg(srcRow + 0), __ldg(srcRow + 1));
        __half2 a23 = __floats2half2_rn(__ldg(srcRow + 2), __ldg(srcRow + 3));
        __half2 a4z = __floats2half2_rn(__ldg(srcRow + 4), 0.0f);
        sts32(xb, *(uint32_t*)&a01);
        sts32(xb + 4, *(uint32_t*)&a23);
        sts32(xb + 8, *(uint32_t*)&a4z);
    }

    const float* bias0 = (const float*)(smc + BIAS0_);
    const float* bias1 = (const float*)(smc + BIAS1_);

    float c0[16], c1[16];
#pragma unroll
    for (int j = 0; j < 16; j++) { c0[j] = 0.0f; c1[j] = 0.0f; }

    __syncthreads();

    int p = 0;
    // ================= encoder =================
    for (int t = 0; t < S_; t++) {
        float x0, x1, x2, x3, x4;
        if (tid < MROWS_ && t + 1 < S_) {
            const float* xp = srcRow + (size_t)(t + 1) * 5;
            x0 = __ldg(xp + 0); x1 = __ldg(xp + 1); x2 = __ldg(xp + 2);
            x3 = __ldg(xp + 3); x4 = __ldg(xp + 4);
        }
        const uint32_t h0r = sb + (p ? H0B_ : H0A_), h0w = sb + (p ? H0A_ : H0B_);
        const uint32_t h1r = sb + (p ? H1B_ : H1A_), h1w = sb + (p ? H1A_ : H1B_);

        lstm_phase<true>(h0r, sb + XT_, sb + WHH0_, sb + W0X_, h0w, bias0, c0, rg, ng, lane);
        __syncthreads();
        if (tid < MROWS_ && t + 1 < S_) {
            uint32_t xb = sb + XT_ + tid * 48;
            __half2 a01 = __floats2half2_rn(x0, x1);
            __half2 a23 = __floats2half2_rn(x2, x3);
            __half2 a4z = __floats2half2_rn(x4, 0.0f);
            sts32(xb, *(uint32_t*)&a01);
            sts32(xb + 4, *(uint32_t*)&a23);
            sts32(xb + 8, *(uint32_t*)&a4z);
        }
        lstm_phase<false>(h0w, h1r, sb + W1A_, sb + W1B_, h1w, bias1, c1, rg, ng, lane);
        __syncthreads();
        p ^= 1;
    }

    // ---------- decoder swap ----------
    fill_wtile(sb + WHH0_, dWhh0);
    fill_wtile(sb + W1A_, dWih1);
    fill_wtile(sb + W1B_, dWhh1);
    fill_w0x(sb + W0X_, dWih0, 1);
    for (int i = tid; i < 256; i += THREADS_) {
        ((float*)(smc + BIAS0_))[i] = __ldg(dbih0 + i) + __ldg(dbhh0 + i);
        ((float*)(smc + BIAS1_))[i] = __ldg(dbih1 + i) + __ldg(dbhh1 + i);
    }
    for (int i = tid; i < 64; i += THREADS_) ((float*)(smc + FCW_))[i] = __ldg(fcW + i);
    if (tid < MROWS_) {
        float xd = __ldg(srcRow + (size_t)(S_ - 1) * 5 + 3);
        uint32_t xb = sb + XT_ + tid * 48;
        __half2 a01 = __floats2half2_rn(xd, 0.0f);
        sts32(xb, *(uint32_t*)&a01);
        sts32(xb + 4, 0u);
        sts32(xb + 8, 0u);
    }
    const float fcb_r = __ldg(fcb);
    const float* fcw_sm = (const float*)(smc + FCW_);
    __syncthreads();

    // ================= decoder =================
    for (int t = 0; t < T_; t++) {
        const uint32_t h0r = sb + (p ? H0B_ : H0A_), h0w = sb + (p ? H0A_ : H0B_);
        const uint32_t h1r = sb + (p ? H1B_ : H1A_), h1w = sb + (p ? H1A_ : H1B_);

        lstm_phase<true>(h0r, sb + XT_, sb + WHH0_, sb + W0X_, h0w, bias0, c0, rg, ng, lane);
        __syncthreads();
        lstm_phase<false>(h0w, h1r, sb + W1A_, sb + W1B_, h1w, bias1, c1, rg, ng, lane);
        __syncthreads();

        if (tid < MROWS_) {
            float acc = fcb_r;
            uint32_t ra = h1w + tid * 128;
#pragma unroll
            for (int c = 0; c < 8; c++) {
                uint4 q = lds128(ra + ((c ^ (tid & 7)) << 4));
                float2 f0 = __half22float2(*(__half2*)&q.x);
                float2 f1 = __half22float2(*(__half2*)&q.y);
                float2 f2 = __half22float2(*(__half2*)&q.z);
                float2 f3 = __half22float2(*(__half2*)&q.w);
                acc = fmaf(f0.x, fcw_sm[c * 8 + 0], acc);
                acc = fmaf(f0.y, fcw_sm[c * 8 + 1], acc);
                acc = fmaf(f1.x, fcw_sm[c * 8 + 2], acc);
                acc = fmaf(f1.y, fcw_sm[c * 8 + 3], acc);
                acc = fmaf(f2.x, fcw_sm[c * 8 + 4], acc);
                acc = fmaf(f2.y, fcw_sm[c * 8 + 5], acc);
                acc = fmaf(f3.x, fcw_sm[c * 8 + 6], acc);
                acc = fmaf(f3.y, fcw_sm[c * 8 + 7], acc);
            }
            out[(size_t)(row0 + tid) * T_ + t] = acc;
            __half2 a01 = __floats2half2_rn(acc, 0.0f);
            sts32(sb + XT_ + tid * 48, *(uint32_t*)&a01);
        }
        __syncthreads();
        p ^= 1;
    }
}

extern "C" void kernel_launch(void* const* d_in, const int* in_sizes, int n_in,
                              void* d_out, int out_size) {
    (void)in_sizes; (void)n_in; (void)out_size;
    cudaFuncSetAttribute(seq2seq_mma, cudaFuncAttributeMaxDynamicSharedMemorySize, SMEM_BYTES);
    seq2seq_mma<<<NCTA_, THREADS_, SMEM_BYTES>>>(
        (const float*)d_in[0],
        (const float*)d_in[1], (const float*)d_in[2], (const float*)d_in[3], (const float*)d_in[4],
        (const float*)d_in[5], (const float*)d_in[6], (const float*)d_in[7], (const float*)d_in[8],
        (const float*)d_in[9], (const float*)d_in[10], (const float*)d_in[11], (const float*)d_in[12],
        (const float*)d_in[13], (const float*)d_in[14], (const float*)d_in[15], (const float*)d_in[16],
        (const float*)d_in[17], (const float*)d_in[18],
        (float*)d_out);
}

// round 6
// speedup vs baseline: 8.8779x; 1.1159x over previous
#include <cuda_runtime.h>
#include <cuda_fp16.h>
#include <cstdint>

#define B_ 16384
#define S_ 336
#define T_ 48
#define MROWS_ 128
#define NCTA_ (B_ / MROWS_)
#define THREADS_ 512

// smem byte offsets
#define H0A_ 0
#define H0B_ 16384
#define H1A_ 32768
#define H1B_ 49152
#define WHH0_ 65536
#define W1A_ 98304
#define W1B_ 131072
#define W0X_ 163840      // 256*48
#define XT0_ 176128      // 128*48
#define XT1_ 182272      // 128*48
#define BIAS0_ 188416    // 1024
#define BIAS1_ 189440    // 1024
#define PART_ 190464     // 128*8 floats = 4096
#define SMEM_BYTES 194560

__device__ __forceinline__ uint32_t smem_u32(const void* p) {
    uint32_t a;
    asm("{ .reg .u64 t; cvta.to.shared.u64 t, %1; cvt.u32.u64 %0, t; }" : "=r"(a) : "l"(p));
    return a;
}
__device__ __forceinline__ void sts32(uint32_t a, uint32_t v) {
    asm volatile("st.shared.u32 [%0], %1;" :: "r"(a), "r"(v) : "memory");
}
#define LDSM4(r0, r1, r2, r3, addr) \
    asm volatile("ldmatrix.sync.aligned.m8n8.x4.shared.b16 {%0,%1,%2,%3}, [%4];" \
        : "=r"(r0), "=r"(r1), "=r"(r2), "=r"(r3) : "r"(addr))

__device__ __forceinline__ void mma16816(float* d, uint32_t a0, uint32_t a1, uint32_t a2, uint32_t a3,
                                         uint32_t b0, uint32_t b1) {
    asm volatile(
        "mma.sync.aligned.m16n8k16.row.col.f32.f16.f16.f32 "
        "{%0,%1,%2,%3},{%4,%5,%6,%7},{%8,%9},{%0,%1,%2,%3};"
        : "+f"(d[0]), "+f"(d[1]), "+f"(d[2]), "+f"(d[3])
        : "r"(a0), "r"(a1), "r"(a2), "r"(a3), "r"(b0), "r"(b1));
}

__device__ __forceinline__ float tanh_a(float x) { float y; asm("tanh.approx.f32 %0,%1;" : "=f"(y) : "f"(x)); return y; }
__device__ __forceinline__ float sig_a(float x) { return fmaf(tanh_a(0.5f * x), 0.5f, 0.5f); }

// permuted gate row: smem row n -> source gate ((n>>3)&3)*64 + (n>>5)*8 + (n&7)
__device__ __forceinline__ int perm_gate(int n) {
    return ((n >> 3) & 3) * 64 + (n >> 5) * 8 + (n & 7);
}

// [256][64] fp16 tile, 128B rows, chunk swizzle c^(row&7), from fp32 row-major [256][64]
__device__ __forceinline__ void fill_wtile(uint32_t dst, const float* __restrict__ W) {
    for (int i = threadIdx.x; i < 256 * 32; i += THREADS_) {
        int n = i >> 5, p = i & 31;
        int gate = perm_gate(n);
        float2 v = *(const float2*)(W + gate * 64 + 2 * p);
        __half2 h = __floats2half2_rn(v.x, v.y);
        int chunk = p >> 2;
        sts32(dst + n * 128 + ((chunk ^ (n & 7)) << 4) + ((p & 3) << 2), *(uint32_t*)&h);
    }
}
// [256][16] fp16 tile, 48B row stride, first `incols` cols from W [256][incols], rest 0
__device__ __forceinline__ void fill_w0x(uint32_t dst, const float* __restrict__ W, int incols) {
    for (int i = threadIdx.x; i < 256 * 8; i += THREADS_) {
        int n = i >> 3, p = i & 7;
        int gate = perm_gate(n);
        int k0 = 2 * p, k1 = 2 * p + 1;
        float v0 = (k0 < incols) ? W[gate * incols + k0] : 0.0f;
        float v1 = (k1 < incols) ? W[gate * incols + k1] : 0.0f;
        __half2 h = __floats2half2_rn(v0, v1);
        sts32(dst + n * 48 + p * 4, *(uint32_t*)&h);
    }
}

// persistent B fragments: [256x64] weight tile -> 32 regs (this warp's 8 units, 4 ksteps)
__device__ __forceinline__ void load_bh(uint32_t wbase, uint32_t* bf, int ng, int lane) {
    const int mat = lane >> 3;
    const int brow = 32 * ng + 8 * (mat >> 1) + (lane & 7);
    const int bxor = lane & 7;
    const int bch = mat & 1;
#pragma unroll
    for (int ks = 0; ks < 4; ks++) {
        uint32_t aA = wbase + brow * 128 + (((2 * ks + bch) ^ bxor) << 4);
        LDSM4(bf[ks * 8 + 0], bf[ks * 8 + 1], bf[ks * 8 + 2], bf[ks * 8 + 3], aA);
        uint32_t aB = wbase + (brow + 16) * 128 + (((2 * ks + bch) ^ bxor) << 4);
        LDSM4(bf[ks * 8 + 4], bf[ks * 8 + 5], bf[ks * 8 + 6], bf[ks * 8 + 7], aB);
    }
}
// x-weight tile [256x16] -> 8 regs
__device__ __forceinline__ void load_bx(uint32_t wbase, uint32_t* bf, int ng, int lane) {
    const int mat = lane >> 3;
    const int brow = 32 * ng + 8 * (mat >> 1) + (lane & 7);
    const int bch = mat & 1;
    uint32_t aA = wbase + brow * 48 + bch * 16;
    LDSM4(bf[0], bf[1], bf[2], bf[3], aA);
    uint32_t aB = wbase + (brow + 16) * 48 + bch * 16;
    LDSM4(bf[4], bf[5], bf[6], bf[7], aB);
}

// one layer tick: this warp's 8 units x 128 rows.
// a1base: h tile (4 ksteps, weights bf1). a2base: XPART ? x tile [128][16] (bf2[0..7])
//         : h tile (bf2[0..31]). Writes h to hwr. FC: fc partials -> part.
template <bool XPART, bool FC>
__device__ __forceinline__ void lstm_tick(uint32_t a1base, uint32_t a2base,
                                          const uint32_t* bf1, const uint32_t* bf2,
                                          uint32_t hwr, const float* biasp, float* cst,
                                          int ng, int lane,
                                          float fw0, float fw1, float* part) {
    const int rowp = lane & 15;
    const int kh = lane >> 4;
    const int uA = 8 * ng + (lane & 3) * 2;
#pragma unroll
    for (int mi = 0; mi < 8; mi++) {
        const int rowbase = mi * 16;
        float acc[4][4];
#pragma unroll
        for (int g = 0; g < 4; g++) {
            float2 bv = *(const float2*)(biasp + g * 64 + uA);
            acc[g][0] = bv.x; acc[g][1] = bv.y;
            acc[g][2] = bv.x; acc[g][3] = bv.y;
        }
        uint32_t a0, a1, a2, a3;
#pragma unroll
        for (int ks = 0; ks < 4; ks++) {
            uint32_t aa = a1base + (rowbase + rowp) * 128 + (((2 * ks + kh) ^ (rowp & 7)) << 4);
            LDSM4(a0, a1, a2, a3, aa);
#pragma unroll
            for (int j = 0; j < 4; j++)
                mma16816(acc[j], a0, a1, a2, a3, bf1[ks * 8 + j * 2], bf1[ks * 8 + j * 2 + 1]);
        }
        if (XPART) {
            uint32_t aa = a2base + (rowbase + rowp) * 48 + kh * 16;
            LDSM4(a0, a1, a2, a3, aa);
#pragma unroll
            for (int j = 0; j < 4; j++)
                mma16816(acc[j], a0, a1, a2, a3, bf2[j * 2], bf2[j * 2 + 1]);
        } else {
#pragma unroll
            for (int ks = 0; ks < 4; ks++) {
                uint32_t aa = a2base + (rowbase + rowp) * 128 + (((2 * ks + kh) ^ (rowp & 7)) << 4);
                LDSM4(a0, a1, a2, a3, aa);
#pragma unroll
                for (int j = 0; j < 4; j++)
                    mma16816(acc[j], a0, a1, a2, a3, bf2[ks * 8 + j * 2], bf2[ks * 8 + j * 2 + 1]);
            }
        }
        float h[4];
#pragma unroll
        for (int d = 0; d < 4; d++) {
            float i_ = sig_a(acc[0][d]);
            float f_ = sig_a(acc[1][d]);
            float g_ = tanh_a(acc[2][d]);
            float o_ = sig_a(acc[3][d]);
            float c = fmaf(f_, cst[mi * 4 + d], i_ * g_);
            cst[mi * 4 + d] = c;
            h[d] = o_ * tanh_a(c);
        }
        uint32_t cx = ((uint32_t)(ng ^ ((lane >> 2) & 7))) << 4;
        uint32_t ba = hwr + (rowbase + (lane >> 2)) * 128 + cx + (lane & 3) * 4;
        __half2 p1 = __floats2half2_rn(h[0], h[1]);
        sts32(ba, *(uint32_t*)&p1);
        __half2 p2 = __floats2half2_rn(h[2], h[3]);
        sts32(ba + 8 * 128, *(uint32_t*)&p2);
        if (FC) {
            float pA = fmaf(h[0], fw0, h[1] * fw1);
            float pB = fmaf(h[2], fw0, h[3] * fw1);
            pA += __shfl_xor_sync(0xffffffffu, pA, 1);
            pA += __shfl_xor_sync(0xffffffffu, pA, 2);
            pB += __shfl_xor_sync(0xffffffffu, pB, 1);
            pB += __shfl_xor_sync(0xffffffffu, pB, 2);
            if ((lane & 3) == 0) {
                int r = rowbase + (lane >> 2);
                part[r * 8 + ng] = pA;
                part[(r + 8) * 8 + ng] = pB;
            }
        }
    }
}

__global__ void __launch_bounds__(THREADS_, 1)
seq2seq_pipe(const float* __restrict__ src,
             const float* __restrict__ eWih0, const float* __restrict__ eWhh0,
             const float* __restrict__ ebih0, const float* __restrict__ ebhh0,
             const float* __restrict__ eWih1, const float* __restrict__ eWhh1,
             const float* __restrict__ ebih1, const float* __restrict__ ebhh1,
             const float* __restrict__ dWih0, const float* __restrict__ dWhh0,
             const float* __restrict__ dbih0, const float* __restrict__ dbhh0,
             const float* __restrict__ dWih1, const float* __restrict__ dWhh1,
             const float* __restrict__ dbih1, const float* __restrict__ dbhh1,
             const float* __restrict__ fcW, const float* __restrict__ fcb,
             float* __restrict__ out) {
    extern __shared__ char smc[];
    const uint32_t sb = smem_u32(smc);
    const int tid = threadIdx.x;
    const int lane = tid & 31;
    const int warp = tid >> 5;
    const bool isL0 = warp < 8;
    const int ng = isL0 ? warp : warp - 8;
    const int row0 = blockIdx.x * MROWS_;

    // zero h buffers and XT buffers
    {
        uint4 z = make_uint4(0, 0, 0, 0);
        uint4* p0 = (uint4*)smc;
        for (int i = tid; i < 65536 / 16; i += THREADS_) p0[i] = z;
        uint4* p1 = (uint4*)(smc + XT0_);
        for (int i = tid; i < 12288 / 16; i += THREADS_) p1[i] = z;
    }
    __syncthreads();

    fill_wtile(sb + WHH0_, eWhh0);
    fill_wtile(sb + W1A_, eWih1);
    fill_wtile(sb + W1B_, eWhh1);
    fill_w0x(sb + W0X_, eWih0, 5);
    for (int i = tid; i < 256; i += THREADS_) {
        ((float*)(smc + BIAS0_))[i] = __ldg(ebih0 + i) + __ldg(ebhh0 + i);
        ((float*)(smc + BIAS1_))[i] = __ldg(ebih1 + i) + __ldg(ebhh1 + i);
    }
    const float* srcRow = src + (size_t)(row0 + tid) * S_ * 5;
    if (tid < MROWS_) {  // x(0) -> XT0
        uint32_t xb = sb + XT0_ + tid * 48;
        __half2 a01 = __floats2half2_rn(__ldg(srcRow + 0), __ldg(srcRow + 1));
        __half2 a23 = __floats2half2_rn(__ldg(srcRow + 2), __ldg(srcRow + 3));
        __half2 a4z = __floats2half2_rn(__ldg(srcRow + 4), 0.0f);
        sts32(xb, *(uint32_t*)&a01);
        sts32(xb + 4, *(uint32_t*)&a23);
        sts32(xb + 8, *(uint32_t*)&a4z);
    }
    __syncthreads();

    // persistent weight fragments
    uint32_t bf1[32], bf2[32];
    if (isL0) {
        load_bh(sb + WHH0_, bf1, ng, lane);
        load_bx(sb + W0X_, bf2, ng, lane);
    } else {
        load_bh(sb + W1A_, bf1, ng, lane);
        load_bh(sb + W1B_, bf2, ng, lane);
    }

    float cst[32];
#pragma unroll
    for (int j = 0; j < 32; j++) cst[j] = 0.0f;

    const float* bias0 = (const float*)(smc + BIAS0_);
    const float* bias1 = (const float*)(smc + BIAS1_);

    // ============ encoder pipeline: ticks k=0..S ============
    // tick k: L0 computes h0(k) (k<S); L1 computes h1(k-1) (k>=1)
    for (int k = 0; k <= S_; k++) {
        const uint32_t h0r = sb + ((k & 1) ? H0A_ : H0B_);
        const uint32_t h0w = sb + ((k & 1) ? H0B_ : H0A_);
        const uint32_t h1r = sb + ((k & 1) ? H1B_ : H1A_);
        const uint32_t h1w = sb + ((k & 1) ? H1A_ : H1B_);
        const uint32_t xtr = sb + ((k & 1) ? XT1_ : XT0_);
        const uint32_t xtw = sb + ((k & 1) ? XT0_ : XT1_);

        float x0, x1, x2, x3, x4;
        const bool pf = (tid < MROWS_) && (k + 1 < S_);
        if (pf) {
            const float* xp = srcRow + (size_t)(k + 1) * 5;
            x0 = __ldg(xp + 0); x1 = __ldg(xp + 1); x2 = __ldg(xp + 2);
            x3 = __ldg(xp + 3); x4 = __ldg(xp + 4);
        }
        if (isL0) {
            if (k < S_)
                lstm_tick<true, false>(h0r, xtr, bf1, bf2, h0w, bias0, cst, ng, lane, 0.f, 0.f, nullptr);
        } else {
            if (k >= 1)
                lstm_tick<false, false>(h0r, h1r, bf1, bf2, h1w, bias1, cst, ng, lane, 0.f, 0.f, nullptr);
        }
        if (pf) {
            __half2 a01 = __floats2half2_rn(x0, x1);
            __half2 a23 = __floats2half2_rn(x2, x3);
            __half2 a4z = __floats2half2_rn(x4, 0.0f);
            uint32_t xb = xtw + tid * 48;
            sts32(xb, *(uint32_t*)&a01);
            sts32(xb + 4, *(uint32_t*)&a23);
            sts32(xb + 8, *(uint32_t*)&a4z);
        }
        __syncthreads();
    }
    // state: h0(S-1) in buf[(S-1)&1]=H0B, h1(S-1) in H1B

    // ============ decoder weight swap ============
    fill_wtile(sb + WHH0_, dWhh0);
    fill_wtile(sb + W1A_, dWih1);
    fill_wtile(sb + W1B_, dWhh1);
    fill_w0x(sb + W0X_, dWih0, 1);
    for (int i = tid; i < 256; i += THREADS_) {
        ((float*)(smc + BIAS0_))[i] = __ldg(dbih0 + i) + __ldg(dbhh0 + i);
        ((float*)(smc + BIAS1_))[i] = __ldg(dbih1 + i) + __ldg(dbhh1 + i);
    }
    {   // zero XT buffers
        uint4 z = make_uint4(0, 0, 0, 0);
        uint4* p1 = (uint4*)(smc + XT0_);
        for (int i = tid; i < 12288 / 16; i += THREADS_) p1[i] = z;
    }
    float fw0 = 0.f, fw1 = 0.f;
    if (!isL0) {
        const int uA = 8 * ng + (lane & 3) * 2;
        fw0 = __ldg(fcW + uA);
        fw1 = __ldg(fcW + uA + 1);
    }
    const float fcb_r = __ldg(fcb);
    __syncthreads();

    if (isL0) {
        load_bh(sb + WHH0_, bf1, ng, lane);
        load_bx(sb + W0X_, bf2, ng, lane);
    } else {
        load_bh(sb + W1A_, bf1, ng, lane);
        load_bh(sb + W1B_, bf2, ng, lane);
    }
    if (tid < MROWS_) {  // x(0) = src[:, -1, 3] -> XT0
        float xd = __ldg(srcRow + (size_t)(S_ - 1) * 5 + 3);
        __half2 hx = __floats2half2_rn(xd, 0.0f);
        sts32(sb + XT0_ + tid * 48, *(uint32_t*)&hx);
    }
    __syncthreads();

    float* part = (float*)(smc + PART_);

    // ============ decoder: sequential phases ============
    for (int t = 0; t < T_; t++) {
        const uint32_t h0r = sb + ((t & 1) ? H0A_ : H0B_);
        const uint32_t h0w = sb + ((t & 1) ? H0B_ : H0A_);
        const uint32_t h1r = sb + ((t & 1) ? H1A_ : H1B_);
        const uint32_t h1w = sb + ((t & 1) ? H1B_ : H1A_);
        const uint32_t xtr = sb + ((t & 1) ? XT1_ : XT0_);

        if (isL0)
            lstm_tick<true, false>(h0r, xtr, bf1, bf2, h0w, bias0, cst, ng, lane, 0.f, 0.f, nullptr);
        __syncthreads();
        if (!isL0)
            lstm_tick<false, true>(h0w, h1r, bf1, bf2, h1w, bias1, cst, ng, lane, fw0, fw1, part);
        __syncthreads();
        if (tid < MROWS_) {
            float4 q0 = *(float4*)(part + tid * 8);
            float4 q1 = *(float4*)(part + tid * 8 + 4);
            float x = q0.x + q0.y + q0.z + q0.w + q1.x + q1.y + q1.z + q1.w + fcb_r;
            out[(size_t)(row0 + tid) * T_ + t] = x;
            __half2 hx = __floats2half2_rn(x, 0.0f);
            sts32(sb + ((t & 1) ? XT0_ : XT1_) + tid * 48, *(uint32_t*)&hx);
        }
        __syncthreads();
    }
}

extern "C" void kernel_launch(void* const* d_in, const int* in_sizes, int n_in,
                              void* d_out, int out_size) {
    (void)in_sizes; (void)n_in; (void)out_size;
    cudaFuncSetAttribute(seq2seq_pipe, cudaFuncAttributeMaxDynamicSharedMemorySize, SMEM_BYTES);
    seq2seq_pipe<<<NCTA_, THREADS_, SMEM_BYTES>>>(
        (const float*)d_in[0],
        (const float*)d_in[1], (const float*)d_in[2], (const float*)d_in[3], (const float*)d_in[4],
        (const float*)d_in[5], (const float*)d_in[6], (const float*)d_in[7], (const float*)d_in[8],
        (const float*)d_in[9], (const float*)d_in[10], (const float*)d_in[11], (const float*)d_in[12],
        (const float*)d_in[13], (const float*)d_in[14], (const float*)d_in[15], (const float*)d_in[16],
        (const float*)d_in[17], (const float*)d_in[18],
        (float*)d_out);
}

// round 8
// speedup vs baseline: 8.9122x; 1.0039x over previous
#include <cuda_runtime.h>
#include <cuda_fp16.h>
#include <cstdint>

#define B_ 16384
#define S_ 336
#define T_ 48
#define MROWS_ 128
#define NCTA_ (B_ / MROWS_)
#define THREADS_ 512

// smem byte offsets
#define H0A_ 0
#define H0B_ 16384
#define H1A_ 32768
#define H1B_ 49152
#define WHH0_ 65536
#define W1A_ 98304
#define W1B_ 131072
#define W0X_ 163840      // 256*48
#define XT0_ 176128      // 128*48
#define XT1_ 182272      // 128*48
#define BIAS0_ 188416    // 1024
#define BIAS1_ 189440    // 1024
#define PART_ 190464     // 128*8 floats = 4096
#define SMEM_BYTES 194560

__device__ __forceinline__ uint32_t smem_u32(const void* p) {
    uint32_t a;
    asm("{ .reg .u64 t; cvta.to.shared.u64 t, %1; cvt.u32.u64 %0, t; }" : "=r"(a) : "l"(p));
    return a;
}
__device__ __forceinline__ void sts32(uint32_t a, uint32_t v) {
    asm volatile("st.shared.u32 [%0], %1;" :: "r"(a), "r"(v) : "memory");
}
#define LDSM4(r0, r1, r2, r3, addr) \
    asm volatile("ldmatrix.sync.aligned.m8n8.x4.shared.b16 {%0,%1,%2,%3}, [%4];" \
        : "=r"(r0), "=r"(r1), "=r"(r2), "=r"(r3) : "r"(addr))

__device__ __forceinline__ void mma16816(float* d, uint32_t a0, uint32_t a1, uint32_t a2, uint32_t a3,
                                         uint32_t b0, uint32_t b1) {
    asm volatile(
        "mma.sync.aligned.m16n8k16.row.col.f32.f16.f16.f32 "
        "{%0,%1,%2,%3},{%4,%5,%6,%7},{%8,%9},{%0,%1,%2,%3};"
        : "+f"(d[0]), "+f"(d[1]), "+f"(d[2]), "+f"(d[3])
        : "r"(a0), "r"(a1), "r"(a2), "r"(a3), "r"(b0), "r"(b1));
}

__device__ __forceinline__ float tanh_a(float x) { float y; asm("tanh.approx.f32 %0,%1;" : "=f"(y) : "f"(x)); return y; }
__device__ __forceinline__ float sig_a(float x) { return fmaf(tanh_a(0.5f * x), 0.5f, 0.5f); }

// permuted gate row: smem row n -> source gate ((n>>3)&3)*64 + (n>>5)*8 + (n&7)
__device__ __forceinline__ int perm_gate(int n) {
    return ((n >> 3) & 3) * 64 + (n >> 5) * 8 + (n & 7);
}

// [256][64] fp16 tile, 128B rows, chunk swizzle c^(row&7), from fp32 row-major [256][64]
__device__ __forceinline__ void fill_wtile(uint32_t dst, const float* __restrict__ W) {
    for (int i = threadIdx.x; i < 256 * 32; i += THREADS_) {
        int n = i >> 5, p = i & 31;
        int gate = perm_gate(n);
        float2 v = *(const float2*)(W + gate * 64 + 2 * p);
        __half2 h = __floats2half2_rn(v.x, v.y);
        int chunk = p >> 2;
        sts32(dst + n * 128 + ((chunk ^ (n & 7)) << 4) + ((p & 3) << 2), *(uint32_t*)&h);
    }
}
// [256][16] fp16 tile, 48B row stride, first `incols` cols from W [256][incols], rest 0
__device__ __forceinline__ void fill_w0x(uint32_t dst, const float* __restrict__ W, int incols) {
    for (int i = threadIdx.x; i < 256 * 8; i += THREADS_) {
        int n = i >> 3, p = i & 7;
        int gate = perm_gate(n);
        int k0 = 2 * p, k1 = 2 * p + 1;
        float v0 = (k0 < incols) ? W[gate * incols + k0] : 0.0f;
        float v1 = (k1 < incols) ? W[gate * incols + k1] : 0.0f;
        __half2 h = __floats2half2_rn(v0, v1);
        sts32(dst + n * 48 + p * 4, *(uint32_t*)&h);
    }
}

// persistent B fragments: [256x64] weight tile -> 32 regs (this warp's 8 units, 4 ksteps)
__device__ __forceinline__ void load_bh(uint32_t wbase, uint32_t* bf, int ng, int lane) {
    const int mat = lane >> 3;
    const int brow = 32 * ng + 8 * (mat >> 1) + (lane & 7);
    const int bxor = lane & 7;
    const int bch = mat & 1;
#pragma unroll
    for (int ks = 0; ks < 4; ks++) {
        uint32_t aA = wbase + brow * 128 + (((2 * ks + bch) ^ bxor) << 4);
        LDSM4(bf[ks * 8 + 0], bf[ks * 8 + 1], bf[ks * 8 + 2], bf[ks * 8 + 3], aA);
        uint32_t aB = wbase + (brow + 16) * 128 + (((2 * ks + bch) ^ bxor) << 4);
        LDSM4(bf[ks * 8 + 4], bf[ks * 8 + 5], bf[ks * 8 + 6], bf[ks * 8 + 7], aB);
    }
}
// x-weight tile [256x16] -> 8 regs
__device__ __forceinline__ void load_bx(uint32_t wbase, uint32_t* bf, int ng, int lane) {
    const int mat = lane >> 3;
    const int brow = 32 * ng + 8 * (mat >> 1) + (lane & 7);
    const int bch = mat & 1;
    uint32_t aA = wbase + brow * 48 + bch * 16;
    LDSM4(bf[0], bf[1], bf[2], bf[3], aA);
    uint32_t aB = wbase + (brow + 16) * 48 + bch * 16;
    LDSM4(bf[4], bf[5], bf[6], bf[7], aB);
}

// one layer tick: this warp's 8 units x 128 rows.
template <bool XPART, bool FC, bool REV>
__device__ __forceinline__ void lstm_tick(uint32_t a1base, uint32_t a2base,
                                          const uint32_t* bf1, const uint32_t* bf2,
                                          uint32_t hwr, const float* biasp, float* cst,
                                          int ng, int lane,
                                          float fw0, float fw1, float* part) {
    const int rowp = lane & 15;
    const int kh = lane >> 4;
    const int uA = 8 * ng + (lane & 3) * 2;
#pragma unroll
    for (int mii = 0; mii < 8; mii++) {
        const int mi = REV ? 7 - mii : mii;
        const int rowbase = mi * 16;
        float acc[4][4];
#pragma unroll
        for (int g = 0; g < 4; g++) {
            float2 bv = *(const float2*)(biasp + g * 64 + uA);
            acc[g][0] = bv.x; acc[g][1] = bv.y;
            acc[g][2] = bv.x; acc[g][3] = bv.y;
        }
        uint32_t a0, a1, a2, a3;
#pragma unroll
        for (int ks = 0; ks < 4; ks++) {
            uint32_t aa = a1base + (rowbase + rowp) * 128 + (((2 * ks + kh) ^ (rowp & 7)) << 4);
            LDSM4(a0, a1, a2, a3, aa);
#pragma unroll
            for (int j = 0; j < 4; j++)
                mma16816(acc[j], a0, a1, a2, a3, bf1[ks * 8 + j * 2], bf1[ks * 8 + j * 2 + 1]);
        }
        if (XPART) {
            uint32_t aa = a2base + (rowbase + rowp) * 48 + kh * 16;
            LDSM4(a0, a1, a2, a3, aa);
#pragma unroll
            for (int j = 0; j < 4; j++)
                mma16816(acc[j], a0, a1, a2, a3, bf2[j * 2], bf2[j * 2 + 1]);
        } else {
#pragma unroll
            for (int ks = 0; ks < 4; ks++) {
                uint32_t aa = a2base + (rowbase + rowp) * 128 + (((2 * ks + kh) ^ (rowp & 7)) << 4);
                LDSM4(a0, a1, a2, a3, aa);
#pragma unroll
                for (int j = 0; j < 4; j++)
                    mma16816(acc[j], a0, a1, a2, a3, bf2[ks * 8 + j * 2], bf2[ks * 8 + j * 2 + 1]);
            }
        }
        // fp32 epilogue (proven 9.2e-5): 4 cells = {row, row+8} x {uA, uA+1}
        float h[4];
#pragma unroll
        for (int d = 0; d < 4; d++) {
            float i_ = sig_a(acc[0][d]);
            float f_ = sig_a(acc[1][d]);
            float g_ = tanh_a(acc[2][d]);
            float o_ = sig_a(acc[3][d]);
            float c = fmaf(f_, cst[mi * 4 + d], i_ * g_);
            cst[mi * 4 + d] = c;
            h[d] = o_ * tanh_a(c);
        }
        uint32_t cx = ((uint32_t)(ng ^ ((lane >> 2) & 7))) << 4;
        uint32_t ba = hwr + (rowbase + (lane >> 2)) * 128 + cx + (lane & 3) * 4;
        __half2 p1 = __floats2half2_rn(h[0], h[1]);
        sts32(ba, *(uint32_t*)&p1);
        __half2 p2 = __floats2half2_rn(h[2], h[3]);
        sts32(ba + 8 * 128, *(uint32_t*)&p2);
        if (FC) {
            float pA = fmaf(h[0], fw0, h[1] * fw1);
            float pB = fmaf(h[2], fw0, h[3] * fw1);
            pA += __shfl_xor_sync(0xffffffffu, pA, 1);
            pA += __shfl_xor_sync(0xffffffffu, pA, 2);
            pB += __shfl_xor_sync(0xffffffffu, pB, 1);
            pB += __shfl_xor_sync(0xffffffffu, pB, 2);
            if ((lane & 3) == 0) {
                int r = rowbase + (lane >> 2);
                part[r * 8 + ng] = pA;
                part[(r + 8) * 8 + ng] = pB;
            }
        }
    }
}

template <bool XPART, bool FC>
__device__ __forceinline__ void lstm_tick_d(uint32_t a1base, uint32_t a2base,
                                            const uint32_t* bf1, const uint32_t* bf2,
                                            uint32_t hwr, const float* biasp, float* cst,
                                            int ng, int lane, int rev,
                                            float fw0, float fw1, float* part) {
    if (rev)
        lstm_tick<XPART, FC, true>(a1base, a2base, bf1, bf2, hwr, biasp, cst, ng, lane, fw0, fw1, part);
    else
        lstm_tick<XPART, FC, false>(a1base, a2base, bf1, bf2, hwr, biasp, cst, ng, lane, fw0, fw1, part);
}

__global__ void __launch_bounds__(THREADS_, 1)
seq2seq_pipe(const float* __restrict__ src,
             const float* __restrict__ eWih0, const float* __restrict__ eWhh0,
             const float* __restrict__ ebih0, const float* __restrict__ ebhh0,
             const float* __restrict__ eWih1, const float* __restrict__ eWhh1,
             const float* __restrict__ ebih1, const float* __restrict__ ebhh1,
             const float* __restrict__ dWih0, const float* __restrict__ dWhh0,
             const float* __restrict__ dbih0, const float* __restrict__ dbhh0,
             const float* __restrict__ dWih1, const float* __restrict__ dWhh1,
             const float* __restrict__ dbih1, const float* __restrict__ dbhh1,
             const float* __restrict__ fcW, const float* __restrict__ fcb,
             float* __restrict__ out) {
    extern __shared__ char smc[];
    const uint32_t sb = smem_u32(smc);
    const int tid = threadIdx.x;
    const int lane = tid & 31;
    const int warp = tid >> 5;
    const bool isL0 = warp < 8;
    const int ng = isL0 ? warp : warp - 8;
    const int rev = (warp >> 2) & 1;
    const int row0 = blockIdx.x * MROWS_;

    // zero h buffers and XT buffers
    {
        uint4 z = make_uint4(0, 0, 0, 0);
        uint4* p0 = (uint4*)smc;
        for (int i = tid; i < 65536 / 16; i += THREADS_) p0[i] = z;
        uint4* p1 = (uint4*)(smc + XT0_);
        for (int i = tid; i < 12288 / 16; i += THREADS_) p1[i] = z;
    }
    __syncthreads();

    fill_wtile(sb + WHH0_, eWhh0);
    fill_wtile(sb + W1A_, eWih1);
    fill_wtile(sb + W1B_, eWhh1);
    fill_w0x(sb + W0X_, eWih0, 5);
    for (int i = tid; i < 256; i += THREADS_) {
        ((float*)(smc + BIAS0_))[i] = __ldg(ebih0 + i) + __ldg(ebhh0 + i);
        ((float*)(smc + BIAS1_))[i] = __ldg(ebih1 + i) + __ldg(ebhh1 + i);
    }
    const float* srcRow = src + (size_t)(row0 + tid) * S_ * 5;
    if (tid < MROWS_) {  // x(0) -> XT0
        uint32_t xb = sb + XT0_ + tid * 48;
        __half2 a01 = __floats2half2_rn(__ldg(srcRow + 0), __ldg(srcRow + 1));
        __half2 a23 = __floats2half2_rn(__ldg(srcRow + 2), __ldg(srcRow + 3));
        __half2 a4z = __floats2half2_rn(__ldg(srcRow + 4), 0.0f);
        sts32(xb, *(uint32_t*)&a01);
        sts32(xb + 4, *(uint32_t*)&a23);
        sts32(xb + 8, *(uint32_t*)&a4z);
    }
    __syncthreads();

    // persistent weight fragments
    uint32_t bf1[32], bf2[32];
    if (isL0) {
        load_bh(sb + WHH0_, bf1, ng, lane);
        load_bx(sb + W0X_, bf2, ng, lane);
    } else {
        load_bh(sb + W1A_, bf1, ng, lane);
        load_bh(sb + W1B_, bf2, ng, lane);
    }

    float cst[32];
#pragma unroll
    for (int j = 0; j < 32; j++) cst[j] = 0.0f;

    const float* bias0 = (const float*)(smc + BIAS0_);
    const float* bias1 = (const float*)(smc + BIAS1_);

    // ============ encoder pipeline: ticks k=0..S ============
    for (int k = 0; k <= S_; k++) {
        const uint32_t h0r = sb + ((k & 1) ? H0A_ : H0B_);
        const uint32_t h0w = sb + ((k & 1) ? H0B_ : H0A_);
        const uint32_t h1r = sb + ((k & 1) ? H1B_ : H1A_);
        const uint32_t h1w = sb + ((k & 1) ? H1A_ : H1B_);
        const uint32_t xtr = sb + ((k & 1) ? XT1_ : XT0_);
        const uint32_t xtw = sb + ((k & 1) ? XT0_ : XT1_);

        float x0, x1, x2, x3, x4;
        const bool pf = (tid < MROWS_) && (k + 1 < S_);
        if (pf) {
            const float* xp = srcRow + (size_t)(k + 1) * 5;
            x0 = __ldg(xp + 0); x1 = __ldg(xp + 1); x2 = __ldg(xp + 2);
            x3 = __ldg(xp + 3); x4 = __ldg(xp + 4);
        }
        if (isL0) {
            if (k < S_)
                lstm_tick_d<true, false>(h0r, xtr, bf1, bf2, h0w, bias0, cst, ng, lane, rev, 0.f, 0.f, nullptr);
        } else {
            if (k >= 1)
                lstm_tick_d<false, false>(h0r, h1r, bf1, bf2, h1w, bias1, cst, ng, lane, rev, 0.f, 0.f, nullptr);
        }
        if (pf) {
            __half2 a01 = __floats2half2_rn(x0, x1);
            __half2 a23 = __floats2half2_rn(x2, x3);
            __half2 a4z = __floats2half2_rn(x4, 0.0f);
            uint32_t xb = xtw + tid * 48;
            sts32(xb, *(uint32_t*)&a01);
            sts32(xb + 4, *(uint32_t*)&a23);
            sts32(xb + 8, *(uint32_t*)&a4z);
        }
        __syncthreads();
    }

    // ============ decoder weight swap ============
    fill_wtile(sb + WHH0_, dWhh0);
    fill_wtile(sb + W1A_, dWih1);
    fill_wtile(sb + W1B_, dWhh1);
    fill_w0x(sb + W0X_, dWih0, 1);
    for (int i = tid; i < 256; i += THREADS_) {
        ((float*)(smc + BIAS0_))[i] = __ldg(dbih0 + i) + __ldg(dbhh0 + i);
        ((float*)(smc + BIAS1_))[i] = __ldg(dbih1 + i) + __ldg(dbhh1 + i);
    }
    {
        uint4 z = make_uint4(0, 0, 0, 0);
        uint4* p1 = (uint4*)(smc + XT0_);
        for (int i = tid; i < 12288 / 16; i += THREADS_) p1[i] = z;
    }
    float fw0 = 0.f, fw1 = 0.f;
    if (!isL0) {
        const int uA = 8 * ng + (lane & 3) * 2;
        fw0 = __ldg(fcW + uA);
        fw1 = __ldg(fcW + uA + 1);
    }
    const float fcb_r = __ldg(fcb);
    __syncthreads();

    if (isL0) {
        load_bh(sb + WHH0_, bf1, ng, lane);
        load_bx(sb + W0X_, bf2, ng, lane);
    } else {
        load_bh(sb + W1A_, bf1, ng, lane);
        load_bh(sb + W1B_, bf2, ng, lane);
    }
    if (tid < MROWS_) {  // x(0) = src[:, -1, 3] -> XT0
        float xd = __ldg(srcRow + (size_t)(S_ - 1) * 5 + 3);
        __half2 hx = __floats2half2_rn(xd, 0.0f);
        sts32(sb + XT0_ + tid * 48, *(uint32_t*)&hx);
    }
    __syncthreads();

    float* part = (float*)(smc + PART_);

    // ============ decoder: sequential phases ============
    for (int t = 0; t < T_; t++) {
        const uint32_t h0r = sb + ((t & 1) ? H0A_ : H0B_);
        const uint32_t h0w = sb + ((t & 1) ? H0B_ : H0A_);
        const uint32_t h1r = sb + ((t & 1) ? H1A_ : H1B_);
        const uint32_t h1w = sb + ((t & 1) ? H1B_ : H1A_);
        const uint32_t xtr = sb + ((t & 1) ? XT1_ : XT0_);

        if (isL0)
            lstm_tick_d<true, false>(h0r, xtr, bf1, bf2, h0w, bias0, cst, ng, lane, rev, 0.f, 0.f, nullptr);
        __syncthreads();
        if (!isL0)
            lstm_tick_d<false, true>(h0w, h1r, bf1, bf2, h1w, bias1, cst, ng, lane, rev, fw0, fw1, part);
        __syncthreads();
        if (tid < MROWS_) {
            float4 q0 = *(float4*)(part + tid * 8);
            float4 q1 = *(float4*)(part + tid * 8 + 4);
            float x = q0.x + q0.y + q0.z + q0.w + q1.x + q1.y + q1.z + q1.w + fcb_r;
            out[(size_t)(row0 + tid) * T_ + t] = x;
            __half2 hx = __floats2half2_rn(x, 0.0f);
            sts32(sb + ((t & 1) ? XT0_ : XT1_) + tid * 48, *(uint32_t*)&hx);
        }
        __syncthreads();
    }
}

extern "C" void kernel_launch(void* const* d_in, const int* in_sizes, int n_in,
                              void* d_out, int out_size) {
    (void)in_sizes; (void)n_in; (void)out_size;
    cudaFuncSetAttribute(seq2seq_pipe, cudaFuncAttributeMaxDynamicSharedMemorySize, SMEM_BYTES);
    seq2seq_pipe<<<NCTA_, THREADS_, SMEM_BYTES>>>(
        (const float*)d_in[0],
        (const float*)d_in[1], (const float*)d_in[2], (const float*)d_in[3], (const float*)d_in[4],
        (const float*)d_in[5], (const float*)d_in[6], (const float*)d_in[7], (const float*)d_in[8],
        (const float*)d_in[9], (const float*)d_in[10], (const float*)d_in[11], (const float*)d_in[12],
        (const float*)d_in[13], (const float*)d_in[14], (const float*)d_in[15], (const float*)d_in[16],
        (const float*)d_in[17], (const float*)d_in[18],
        (float*)d_out);
}

// round 10
// speedup vs baseline: 9.1933x; 1.0315x over previous
#include <cuda_runtime.h>
#include <cuda_fp16.h>
#include <cstdint>

#define B_ 16384
#define S_ 336
#define T_ 48
#define MROWS_ 128
#define NCTA_ (B_ / MROWS_)
#define THREADS_ 512

// smem byte offsets
#define H0A_ 0
#define H0B_ 16384
#define H1A_ 32768
#define H1B_ 49152
#define WHH0_ 65536
#define W1A_ 98304
#define W1B_ 131072
#define W0X_ 163840      // 256*48
#define XT0_ 176128      // 128*48
#define XT1_ 182272      // 128*48
#define BIAS0_ 188416    // 1024
#define BIAS1_ 189440    // 1024
#define PART_ 190464     // 128*8 floats = 4096
#define SMEM_BYTES 194560

__device__ __forceinline__ uint32_t smem_u32(const void* p) {
    uint32_t a;
    asm("{ .reg .u64 t; cvta.to.shared.u64 t, %1; cvt.u32.u64 %0, t; }" : "=r"(a) : "l"(p));
    return a;
}
__device__ __forceinline__ void sts32(uint32_t a, uint32_t v) {
    asm volatile("st.shared.u32 [%0], %1;" :: "r"(a), "r"(v) : "memory");
}
#define LDSM4(r0, r1, r2, r3, addr) \
    asm volatile("ldmatrix.sync.aligned.m8n8.x4.shared.b16 {%0,%1,%2,%3}, [%4];" \
        : "=r"(r0), "=r"(r1), "=r"(r2), "=r"(r3) : "r"(addr))

__device__ __forceinline__ void mma16816(float* d, uint32_t a0, uint32_t a1, uint32_t a2, uint32_t a3,
                                         uint32_t b0, uint32_t b1) {
    asm volatile(
        "mma.sync.aligned.m16n8k16.row.col.f32.f16.f16.f32 "
        "{%0,%1,%2,%3},{%4,%5,%6,%7},{%8,%9},{%0,%1,%2,%3};"
        : "+f"(d[0]), "+f"(d[1]), "+f"(d[2]), "+f"(d[3])
        : "r"(a0), "r"(a1), "r"(a2), "r"(a3), "r"(b0), "r"(b1));
}

__device__ __forceinline__ float tanh_a(float x) { float y; asm("tanh.approx.f32 %0,%1;" : "=f"(y) : "f"(x)); return y; }
__device__ __forceinline__ float sig_a(float x) { return fmaf(tanh_a(0.5f * x), 0.5f, 0.5f); }

// permuted gate row: smem row n -> source gate ((n>>3)&3)*64 + (n>>5)*8 + (n&7)
__device__ __forceinline__ int perm_gate(int n) {
    return ((n >> 3) & 3) * 64 + (n >> 5) * 8 + (n & 7);
}

// [256][64] fp16 tile, 128B rows, chunk swizzle c^(row&7), from fp32 row-major [256][64]
__device__ __forceinline__ void fill_wtile(uint32_t dst, const float* __restrict__ W) {
    for (int i = threadIdx.x; i < 256 * 32; i += THREADS_) {
        int n = i >> 5, p = i & 31;
        int gate = perm_gate(n);
        float2 v = *(const float2*)(W + gate * 64 + 2 * p);
        __half2 h = __floats2half2_rn(v.x, v.y);
        int chunk = p >> 2;
        sts32(dst + n * 128 + ((chunk ^ (n & 7)) << 4) + ((p & 3) << 2), *(uint32_t*)&h);
    }
}
// [256][16] fp16 tile, 48B row stride, first `incols` cols from W [256][incols], rest 0
__device__ __forceinline__ void fill_w0x(uint32_t dst, const float* __restrict__ W, int incols) {
    for (int i = threadIdx.x; i < 256 * 8; i += THREADS_) {
        int n = i >> 3, p = i & 7;
        int gate = perm_gate(n);
        int k0 = 2 * p, k1 = 2 * p + 1;
        float v0 = (k0 < incols) ? W[gate * incols + k0] : 0.0f;
        float v1 = (k1 < incols) ? W[gate * incols + k1] : 0.0f;
        __half2 h = __floats2half2_rn(v0, v1);
        sts32(dst + n * 48 + p * 4, *(uint32_t*)&h);
    }
}

// persistent B fragments: [256x64] weight tile -> 32 regs (this warp's 8 units, 4 ksteps)
__device__ __forceinline__ void load_bh(uint32_t wbase, uint32_t* bf, int ng, int lane) {
    const int mat = lane >> 3;
    const int brow = 32 * ng + 8 * (mat >> 1) + (lane & 7);
    const int bxor = lane & 7;
    const int bch = mat & 1;
#pragma unroll
    for (int ks = 0; ks < 4; ks++) {
        uint32_t aA = wbase + brow * 128 + (((2 * ks + bch) ^ bxor) << 4);
        LDSM4(bf[ks * 8 + 0], bf[ks * 8 + 1], bf[ks * 8 + 2], bf[ks * 8 + 3], aA);
        uint32_t aB = wbase + (brow + 16) * 128 + (((2 * ks + bch) ^ bxor) << 4);
        LDSM4(bf[ks * 8 + 4], bf[ks * 8 + 5], bf[ks * 8 + 6], bf[ks * 8 + 7], aB);
    }
}
// x-weight tile [256x16] -> 8 regs
__device__ __forceinline__ void load_bx(uint32_t wbase, uint32_t* bf, int ng, int lane) {
    const int mat = lane >> 3;
    const int brow = 32 * ng + 8 * (mat >> 1) + (lane & 7);
    const int bch = mat & 1;
    uint32_t aA = wbase + brow * 48 + bch * 16;
    LDSM4(bf[0], bf[1], bf[2], bf[3], aA);
    uint32_t aB = wbase + (brow + 16) * 48 + bch * 16;
    LDSM4(bf[4], bf[5], bf[6], bf[7], aB);
}

// one layer tick, software-pipelined: MMA(k+1) issued before EPI(k).
// Epilogue math is the PROVEN fp32 path (rel_err 9.2e-5) — only the h store is half.
template <bool XPART, bool FC>
__device__ __forceinline__ void lstm_tick(uint32_t a1base, uint32_t a2base,
                                          const uint32_t* bf1, const uint32_t* bf2x,
                                          uint32_t w2base,
                                          uint32_t hwr, const float* biasp, float* cst,
                                          int ng, int lane,
                                          float fw0, float fw1, float* part) {
    const int rowp = lane & 15;
    const int kh = lane >> 4;
    const int uA = 8 * ng + (lane & 3) * 2;
    const int mat = lane >> 3;
    const int brow = 32 * ng + 8 * (mat >> 1) + (lane & 7);
    const int bxor = lane & 7;
    const int bch = mat & 1;

    float acc[2][4][4];

    auto mma_block = [&](int mi, int buf) {
        const int rowbase = mi * 16;
        float (*a)[4] = acc[buf];
#pragma unroll
        for (int g = 0; g < 4; g++) {
            float2 bv = *(const float2*)(biasp + g * 64 + uA);
            a[g][0] = bv.x; a[g][1] = bv.y;
            a[g][2] = bv.x; a[g][3] = bv.y;
        }
        uint32_t a0, a1, a2, a3;
#pragma unroll
        for (int ks = 0; ks < 4; ks++) {
            uint32_t aa = a1base + (rowbase + rowp) * 128 + (((2 * ks + kh) ^ (rowp & 7)) << 4);
            LDSM4(a0, a1, a2, a3, aa);
#pragma unroll
            for (int j = 0; j < 4; j++)
                mma16816(a[j], a0, a1, a2, a3, bf1[ks * 8 + j * 2], bf1[ks * 8 + j * 2 + 1]);
        }
        if (XPART) {
            uint32_t aa = a2base + (rowbase + rowp) * 48 + kh * 16;
            LDSM4(a0, a1, a2, a3, aa);
#pragma unroll
            for (int j = 0; j < 4; j++)
                mma16816(a[j], a0, a1, a2, a3, bf2x[j * 2], bf2x[j * 2 + 1]);
        } else {
#pragma unroll
            for (int ks = 0; ks < 4; ks++) {
                uint32_t aa = a2base + (rowbase + rowp) * 128 + (((2 * ks + kh) ^ (rowp & 7)) << 4);
                LDSM4(a0, a1, a2, a3, aa);
                uint32_t b0, b1, b2, b3, b4, b5, b6, b7;
                uint32_t wA = w2base + brow * 128 + (((2 * ks + bch) ^ bxor) << 4);
                LDSM4(b0, b1, b2, b3, wA);
                uint32_t wB = w2base + (brow + 16) * 128 + (((2 * ks + bch) ^ bxor) << 4);
                LDSM4(b4, b5, b6, b7, wB);
                mma16816(a[0], a0, a1, a2, a3, b0, b1);
                mma16816(a[1], a0, a1, a2, a3, b2, b3);
                mma16816(a[2], a0, a1, a2, a3, b4, b5);
                mma16816(a[3], a0, a1, a2, a3, b6, b7);
            }
        }
    };

    auto epi = [&](int mi, int buf) {
        const int rowbase = mi * 16;
        float (*a)[4] = acc[buf];
        float h[4];
#pragma unroll
        for (int d = 0; d < 4; d++) {
            float i_ = sig_a(a[0][d]);
            float f_ = sig_a(a[1][d]);
            float g_ = tanh_a(a[2][d]);
            float o_ = sig_a(a[3][d]);
            float c = fmaf(f_, cst[mi * 4 + d], i_ * g_);
            cst[mi * 4 + d] = c;
            h[d] = o_ * tanh_a(c);
        }
        uint32_t cx = ((uint32_t)(ng ^ ((lane >> 2) & 7))) << 4;
        uint32_t ba = hwr + (rowbase + (lane >> 2)) * 128 + cx + (lane & 3) * 4;
        __half2 p1 = __floats2half2_rn(h[0], h[1]);
        sts32(ba, *(uint32_t*)&p1);
        __half2 p2 = __floats2half2_rn(h[2], h[3]);
        sts32(ba + 8 * 128, *(uint32_t*)&p2);
        if (FC) {
            float pA = fmaf(h[0], fw0, h[1] * fw1);
            float pB = fmaf(h[2], fw0, h[3] * fw1);
            pA += __shfl_xor_sync(0xffffffffu, pA, 1);
            pA += __shfl_xor_sync(0xffffffffu, pA, 2);
            pB += __shfl_xor_sync(0xffffffffu, pB, 1);
            pB += __shfl_xor_sync(0xffffffffu, pB, 2);
            if ((lane & 3) == 0) {
                int r = rowbase + (lane >> 2);
                part[r * 8 + ng] = pA;
                part[(r + 8) * 8 + ng] = pB;
            }
        }
    };

    mma_block(0, 0);
#pragma unroll
    for (int mii = 0; mii < 8; mii++) {
        if (mii < 7) mma_block(mii + 1, (mii + 1) & 1);
        epi(mii, mii & 1);
    }
}

__global__ void __launch_bounds__(THREADS_, 1)
seq2seq_pipe(const float* __restrict__ src,
             const float* __restrict__ eWih0, const float* __restrict__ eWhh0,
             const float* __restrict__ ebih0, const float* __restrict__ ebhh0,
             const float* __restrict__ eWih1, const float* __restrict__ eWhh1,
             const float* __restrict__ ebih1, const float* __restrict__ ebhh1,
             const float* __restrict__ dWih0, const float* __restrict__ dWhh0,
             const float* __restrict__ dbih0, const float* __restrict__ dbhh0,
             const float* __restrict__ dWih1, const float* __restrict__ dWhh1,
             const float* __restrict__ dbih1, const float* __restrict__ dbhh1,
             const float* __restrict__ fcW, const float* __restrict__ fcb,
             float* __restrict__ out) {
    extern __shared__ char smc[];
    const uint32_t sb = smem_u32(smc);
    const int tid = threadIdx.x;
    const int lane = tid & 31;
    const int warp = tid >> 5;
    const bool isL0 = warp < 8;
    const int ng = isL0 ? warp : warp - 8;
    const int row0 = blockIdx.x * MROWS_;

    // zero h buffers and XT buffers
    {
        uint4 z = make_uint4(0, 0, 0, 0);
        uint4* p0 = (uint4*)smc;
        for (int i = tid; i < 65536 / 16; i += THREADS_) p0[i] = z;
        uint4* p1 = (uint4*)(smc + XT0_);
        for (int i = tid; i < 12288 / 16; i += THREADS_) p1[i] = z;
    }
    __syncthreads();

    fill_wtile(sb + WHH0_, eWhh0);
    fill_wtile(sb + W1A_, eWih1);
    fill_wtile(sb + W1B_, eWhh1);
    fill_w0x(sb + W0X_, eWih0, 5);
    for (int i = tid; i < 256; i += THREADS_) {
        ((float*)(smc + BIAS0_))[i] = __ldg(ebih0 + i) + __ldg(ebhh0 + i);
        ((float*)(smc + BIAS1_))[i] = __ldg(ebih1 + i) + __ldg(ebhh1 + i);
    }
    const float* srcRow = src + (size_t)(row0 + tid) * S_ * 5;
    if (tid < MROWS_) {  // x(0) -> XT0
        uint32_t xb = sb + XT0_ + tid * 48;
        __half2 a01 = __floats2half2_rn(__ldg(srcRow + 0), __ldg(srcRow + 1));
        __half2 a23 = __floats2half2_rn(__ldg(srcRow + 2), __ldg(srcRow + 3));
        __half2 a4z = __floats2half2_rn(__ldg(srcRow + 4), 0.0f);
        sts32(xb, *(uint32_t*)&a01);
        sts32(xb + 4, *(uint32_t*)&a23);
        sts32(xb + 8, *(uint32_t*)&a4z);
    }
    __syncthreads();

    // persistent weight fragments: bf1 hoisted for both layers; bf2 hoisted only for L0 (x-weights)
    uint32_t bf1[32], bf2x[8];
    if (isL0) {
        load_bh(sb + WHH0_, bf1, ng, lane);
        load_bx(sb + W0X_, bf2x, ng, lane);
    } else {
        load_bh(sb + W1A_, bf1, ng, lane);
    }

    float cst[32];
#pragma unroll
    for (int j = 0; j < 32; j++) cst[j] = 0.0f;

    const float* bias0 = (const float*)(smc + BIAS0_);
    const float* bias1 = (const float*)(smc + BIAS1_);

    // ============ encoder pipeline: ticks k=0..S ============
    for (int k = 0; k <= S_; k++) {
        const uint32_t h0r = sb + ((k & 1) ? H0A_ : H0B_);
        const uint32_t h0w = sb + ((k & 1) ? H0B_ : H0A_);
        const uint32_t h1r = sb + ((k & 1) ? H1B_ : H1A_);
        const uint32_t h1w = sb + ((k & 1) ? H1A_ : H1B_);
        const uint32_t xtr = sb + ((k & 1) ? XT1_ : XT0_);
        const uint32_t xtw = sb + ((k & 1) ? XT0_ : XT1_);

        float x0, x1, x2, x3, x4;
        const bool pf = (tid < MROWS_) && (k + 1 < S_);
        if (pf) {
            const float* xp = srcRow + (size_t)(k + 1) * 5;
            x0 = __ldg(xp + 0); x1 = __ldg(xp + 1); x2 = __ldg(xp + 2);
            x3 = __ldg(xp + 3); x4 = __ldg(xp + 4);
        }
        if (isL0) {
            if (k < S_)
                lstm_tick<true, false>(h0r, xtr, bf1, bf2x, 0, h0w, bias0, cst, ng, lane, 0.f, 0.f, nullptr);
        } else {
            if (k >= 1)
                lstm_tick<false, false>(h0r, h1r, bf1, nullptr, sb + W1B_, h1w, bias1, cst, ng, lane, 0.f, 0.f, nullptr);
        }
        if (pf) {
            __half2 a01 = __floats2half2_rn(x0, x1);
            __half2 a23 = __floats2half2_rn(x2, x3);
            __half2 a4z = __floats2half2_rn(x4, 0.0f);
            uint32_t xb = xtw + tid * 48;
            sts32(xb, *(uint32_t*)&a01);
            sts32(xb + 4, *(uint32_t*)&a23);
            sts32(xb + 8, *(uint32_t*)&a4z);
        }
        __syncthreads();
    }

    // ============ decoder weight swap ============
    fill_wtile(sb + WHH0_, dWhh0);
    fill_wtile(sb + W1A_, dWih1);
    fill_wtile(sb + W1B_, dWhh1);
    fill_w0x(sb + W0X_, dWih0, 1);
    for (int i = tid; i < 256; i += THREADS_) {
        ((float*)(smc + BIAS0_))[i] = __ldg(dbih0 + i) + __ldg(dbhh0 + i);
        ((float*)(smc + BIAS1_))[i] = __ldg(dbih1 + i) + __ldg(dbhh1 + i);
    }
    {
        uint4 z = make_uint4(0, 0, 0, 0);
        uint4* p1 = (uint4*)(smc + XT0_);
        for (int i = tid; i < 12288 / 16; i += THREADS_) p1[i] = z;
    }
    float fw0 = 0.f, fw1 = 0.f;
    if (!isL0) {
        const int uAa = 8 * ng + (lane & 3) * 2;
        fw0 = __ldg(fcW + uAa);
        fw1 = __ldg(fcW + uAa + 1);
    }
    const float fcb_r = __ldg(fcb);
    __syncthreads();

    if (isL0) {
        load_bh(sb + WHH0_, bf1, ng, lane);
        load_bx(sb + W0X_, bf2x, ng, lane);
    } else {
        load_bh(sb + W1A_, bf1, ng, lane);
    }
    if (tid < MROWS_) {  // x(0) = src[:, -1, 3] -> XT0
        float xd = __ldg(srcRow + (size_t)(S_ - 1) * 5 + 3);
        __half2 hx = __floats2half2_rn(xd, 0.0f);
        sts32(sb + XT0_ + tid * 48, *(uint32_t*)&hx);
    }
    __syncthreads();

    float* part = (float*)(smc + PART_);

    // ============ decoder: sequential phases ============
    for (int t = 0; t < T_; t++) {
        const uint32_t h0r = sb + ((t & 1) ? H0A_ : H0B_);
        const uint32_t h0w = sb + ((t & 1) ? H0B_ : H0A_);
        const uint32_t h1r = sb + ((t & 1) ? H1A_ : H1B_);
        const uint32_t h1w = sb + ((t & 1) ? H1B_ : H1A_);
        const uint32_t xtr = sb + ((t & 1) ? XT1_ : XT0_);

        if (isL0)
            lstm_tick<true, false>(h0r, xtr, bf1, bf2x, 0, h0w, bias0, cst, ng, lane, 0.f, 0.f, nullptr);
        __syncthreads();
        if (!isL0)
            lstm_tick<false, true>(h0w, h1r, bf1, nullptr, sb + W1B_, h1w, bias1, cst, ng, lane, fw0, fw1, part);
        __syncthreads();
        if (tid < MROWS_) {
            float4 q0 = *(float4*)(part + tid * 8);
            float4 q1 = *(float4*)(part + tid * 8 + 4);
            float x = q0.x + q0.y + q0.z + q0.w + q1.x + q1.y + q1.z + q1.w + fcb_r;
            out[(size_t)(row0 + tid) * T_ + t] = x;
            __half2 hx = __floats2half2_rn(x, 0.0f);
            sts32(sb + ((t & 1) ? XT0_ : XT1_) + tid * 48, *(uint32_t*)&hx);
        }
        __syncthreads();
    }
}

extern "C" void kernel_launch(void* const* d_in, const int* in_sizes, int n_in,
                              void* d_out, int out_size) {
    (void)in_sizes; (void)n_in; (void)out_size;
    cudaFuncSetAttribute(seq2seq_pipe, cudaFuncAttributeMaxDynamicSharedMemorySize, SMEM_BYTES);
    seq2seq_pipe<<<NCTA_, THREADS_, SMEM_BYTES>>>(
        (const float*)d_in[0],
        (const float*)d_in[1], (const float*)d_in[2], (const float*)d_in[3], (const float*)d_in[4],
        (const float*)d_in[5], (const float*)d_in[6], (const float*)d_in[7], (const float*)d_in[8],
        (const float*)d_in[9], (const float*)d_in[10], (const float*)d_in[11], (const float*)d_in[12],
        (const float*)d_in[13], (const float*)d_in[14], (const float*)d_in[15], (const float*)d_in[16],
        (const float*)d_in[17], (const float*)d_in[18],
        (float*)d_out);
}